// round 6
// baseline (speedup 1.0000x reference)
#include <cuda_runtime.h>
#include <cuda_fp16.h>
#include <math.h>
#include <stdint.h>

// Problem dims (fixed by the reference)
#define B_   4
#define T_   2048
#define D_   1024
#define H_   16
#define HD_  64
#define M_TOT (B_*T_)   // 8192
#define DD_  (D_*D_)

// ---------------------------------------------------------------------------
// Device-global scratch (allocation-free rule). fp16; hi/lo only on A-side.
// ---------------------------------------------------------------------------
__device__ __align__(128) __half g_xh [M_TOT * D_];
__device__ __align__(128) __half g_xl [M_TOT * D_];
__device__ __align__(128) __half g_qh [M_TOT * D_];
__device__ __align__(128) __half g_ql [M_TOT * D_];
__device__ __align__(128) __half g_kh [M_TOT * D_];
__device__ __align__(128) __half g_vh [M_TOT * D_];
__device__ __align__(128) __half g_aoh[M_TOT * D_];
__device__ __align__(128) __half g_aol[M_TOT * D_];
__device__ __align__(128) __half g_wh [4 * DD_];   // q,k,v,o (hi only)

// ---------------------------------------------------------------------------
// PTX helpers (target-independent, sm_80-era)
// ---------------------------------------------------------------------------
__device__ __forceinline__ uint32_t smem_u32(const void* p) {
    uint32_t a;
    asm("{ .reg .u64 t; cvta.to.shared.u64 t, %1; cvt.u32.u64 %0, t; }"
        : "=r"(a) : "l"(p));
    return a;
}

__device__ __forceinline__ void cp16(uint32_t dst, const void* src) {
    asm volatile("cp.async.cg.shared.global [%0], [%1], 16;"
                 :: "r"(dst), "l"(src));
}
#define CP_COMMIT() asm volatile("cp.async.commit_group;" ::: "memory")
#define CP_WAIT(n)  asm volatile("cp.async.wait_group %0;" :: "n"(n) : "memory")

__device__ __forceinline__ void ldsm4(uint32_t& r0, uint32_t& r1,
                                      uint32_t& r2, uint32_t& r3, uint32_t a) {
    asm volatile("ldmatrix.sync.aligned.m8n8.x4.shared.b16 {%0,%1,%2,%3}, [%4];"
                 : "=r"(r0), "=r"(r1), "=r"(r2), "=r"(r3) : "r"(a));
}
__device__ __forceinline__ void ldsm4t(uint32_t& r0, uint32_t& r1,
                                       uint32_t& r2, uint32_t& r3, uint32_t a) {
    asm volatile("ldmatrix.sync.aligned.m8n8.x4.trans.shared.b16 {%0,%1,%2,%3}, [%4];"
                 : "=r"(r0), "=r"(r1), "=r"(r2), "=r"(r3) : "r"(a));
}

__device__ __forceinline__ void mma16816(float* c,
                                         uint32_t a0, uint32_t a1,
                                         uint32_t a2, uint32_t a3,
                                         uint32_t b0, uint32_t b1) {
    asm volatile("mma.sync.aligned.m16n8k16.row.col.f32.f16.f16.f32 "
                 "{%0,%1,%2,%3}, {%4,%5,%6,%7}, {%8,%9}, {%0,%1,%2,%3};"
                 : "+f"(c[0]), "+f"(c[1]), "+f"(c[2]), "+f"(c[3])
                 : "r"(a0), "r"(a1), "r"(a2), "r"(a3), "r"(b0), "r"(b1));
}

// fp32 pair -> packed fp16 hi pair + lo pair
__device__ __forceinline__ void split_pack2(float x, float y,
                                            uint32_t& hp, uint32_t& lp) {
    __half hx = __float2half(x);
    __half hy = __float2half(y);
    __half lx = __float2half(x - __half2float(hx));
    __half ly = __float2half(y - __half2float(hy));
    hp = (uint32_t)__half_as_ushort(hx) | ((uint32_t)__half_as_ushort(hy) << 16);
    lp = (uint32_t)__half_as_ushort(lx) | ((uint32_t)__half_as_ushort(ly) << 16);
}
__device__ __forceinline__ uint32_t pack2h(float x, float y) {
    return (uint32_t)__half_as_ushort(__float2half(x)) |
           ((uint32_t)__half_as_ushort(__float2half(y)) << 16);
}

// ---------------------------------------------------------------------------
// Input conversion kernels
// ---------------------------------------------------------------------------
__global__ void __launch_bounds__(256)
split_x_kernel(const float* __restrict__ src)
{
    int i = blockIdx.x * 256 + threadIdx.x;
    if (i >= M_TOT * D_ / 2) return;
    float2 a = ((const float2*)src)[i];
    uint32_t hp, lp;
    split_pack2(a.x, a.y, hp, lp);
    ((uint32_t*)g_xh)[i] = hp;
    ((uint32_t*)g_xl)[i] = lp;
}

__global__ void __launch_bounds__(256)
split_w4_kernel(const float* __restrict__ wq, const float* __restrict__ wk,
                const float* __restrict__ wv, const float* __restrict__ wo)
{
    int i = blockIdx.x * 256 + threadIdx.x;           // < DD_/2 exactly
    const float* srcs[4] = { wq, wk, wv, wo };
    float2 a = ((const float2*)srcs[blockIdx.y])[i];
    ((uint32_t*)(g_wh + (size_t)blockIdx.y * DD_))[i] = pack2h(a.x, a.y);
}

// ---------------------------------------------------------------------------
// fp16 2-pass GEMM: C[M,N] = (Ah+Al)[M,K] * Wh[N,K]^T
// CTA tile 128x256, BK=32, 8 warps (4m x 2n), 4-stage cp.async pipeline.
// MODE 0: fp32 out. 1: RoPE+scale hi/lo. 2: hi only. 3: RoPE hi only.
// ---------------------------------------------------------------------------
#define ROWB 40                         // smem row stride in halfwords (80 B)
#define S_AH 0
#define S_AL (128 * ROWB)               // 5120 h
#define S_BH (256 * ROWB)               // 10240 h
#define STAGE_E (512 * ROWB)            // 20480 h
#define STAGE_B (STAGE_E * 2)           // 40960 B
#define NSTG 4
#define GEMM_SMEM_B (NSTG * STAGE_B)    // 163840 B

template <int MODE>
__device__ void gemm_core(const __half* __restrict__ Ah,
                          const __half* __restrict__ Al,
                          const __half* __restrict__ Bh,
                          float* __restrict__ Cf,
                          __half* __restrict__ Ch,
                          __half* __restrict__ Cl,
                          const float* __restrict__ cosp,
                          const float* __restrict__ sinp,
                          float qscale)
{
    extern __shared__ __align__(128) char smem[];
    const uint32_t sb = smem_u32(smem);
    const int tid  = threadIdx.x;
    const int lane = tid & 31;
    const int wid  = tid >> 5;
    const int warp_m = wid & 3;         // 32 rows
    const int warp_n = wid >> 2;        // 128 cols
    const int m0 = blockIdx.y * 128;
    const int n0 = blockIdx.x * 256;

    const int a_row = lane & 15;
    const int a_col = (lane >> 4) << 3;
    const int b_row = (lane & 7) + ((lane >> 4) << 3);
    const int b_col = ((lane >> 3) & 1) << 3;

    float acc[2][16][4];
#pragma unroll
    for (int mt = 0; mt < 2; mt++)
#pragma unroll
        for (int nt = 0; nt < 16; nt++)
#pragma unroll
            for (int r = 0; r < 4; r++) acc[mt][nt][r] = 0.f;

    auto issue = [&](int st, int k0) {
        const uint32_t dstb = sb + st * STAGE_B;
#pragma unroll
        for (int i = 0; i < 8; i++) {
            int v = tid + i * 256;
            if (i < 2) {                    // Ah: v in [0,512)
                int r = v >> 2, c = v & 3;
                cp16(dstb + (uint32_t)(S_AH + r * ROWB + c * 8) * 2,
                     Ah + (size_t)(m0 + r) * D_ + k0 + c * 8);
            } else if (i < 4) {             // Al: v-512 in [0,512)
                int u = v - 512;
                int r = u >> 2, c = u & 3;
                cp16(dstb + (uint32_t)(S_AL + r * ROWB + c * 8) * 2,
                     Al + (size_t)(m0 + r) * D_ + k0 + c * 8);
            } else {                        // Bh: v-1024 in [0,1024)
                int u = v - 1024;
                int r = u >> 2, c = u & 3;
                cp16(dstb + (uint32_t)(S_BH + r * ROWB + c * 8) * 2,
                     Bh + (size_t)(n0 + r) * D_ + k0 + c * 8);
            }
        }
        CP_COMMIT();
    };

    const int NIT = D_ / 32;                // 32
    issue(0, 0);
    issue(1, 32);
    issue(2, 64);

    for (int ic = 0; ic < NIT; ic++) {
        if (ic + 2 < NIT)      { CP_WAIT(2); }
        else if (ic + 1 < NIT) { CP_WAIT(1); }
        else                   { CP_WAIT(0); }
        __syncthreads();
        if (ic + 3 < NIT) issue((ic + 3) & 3, (ic + 3) * 32);

        const uint32_t sa = sb + (ic & 3) * STAGE_B;
#pragma unroll
        for (int ks = 0; ks < 2; ks++) {
            uint32_t ah[2][4], al_[2][4];
#pragma unroll
            for (int mt = 0; mt < 2; mt++) {
                uint32_t ra = sa + (uint32_t)((warp_m * 32 + mt * 16 + a_row) * ROWB
                                              + ks * 16 + a_col) * 2;
                ldsm4(ah[mt][0],  ah[mt][1],  ah[mt][2],  ah[mt][3],  ra + S_AH * 2);
                ldsm4(al_[mt][0], al_[mt][1], al_[mt][2], al_[mt][3], ra + S_AL * 2);
            }
#pragma unroll
            for (int pt = 0; pt < 8; pt++) {
                uint32_t b0, b1, b2, b3;
                uint32_t rb = sa + (uint32_t)(S_BH + (warp_n * 128 + pt * 16 + b_row) * ROWB
                                              + ks * 16 + b_col) * 2;
                ldsm4(b0, b1, b2, b3, rb);
#pragma unroll
                for (int mt = 0; mt < 2; mt++) {
                    mma16816(acc[mt][2 * pt],     ah[mt][0],  ah[mt][1],  ah[mt][2],  ah[mt][3],  b0, b1);
                    mma16816(acc[mt][2 * pt],     al_[mt][0], al_[mt][1], al_[mt][2], al_[mt][3], b0, b1);
                    mma16816(acc[mt][2 * pt + 1], ah[mt][0],  ah[mt][1],  ah[mt][2],  ah[mt][3],  b2, b3);
                    mma16816(acc[mt][2 * pt + 1], al_[mt][0], al_[mt][1], al_[mt][2], al_[mt][3], b2, b3);
                }
            }
        }
        __syncthreads();
    }

    const int g = lane >> 2, t2 = lane & 3;
    if (MODE == 0) {
#pragma unroll
        for (int mt = 0; mt < 2; mt++) {
            int r0 = m0 + warp_m * 32 + mt * 16 + g;
#pragma unroll
            for (int nt = 0; nt < 16; nt++) {
                int col = n0 + warp_n * 128 + nt * 8 + t2 * 2;
                *(float2*)(Cf + (size_t)r0 * D_ + col) =
                    make_float2(acc[mt][nt][0], acc[mt][nt][1]);
                *(float2*)(Cf + (size_t)(r0 + 8) * D_ + col) =
                    make_float2(acc[mt][nt][2], acc[mt][nt][3]);
            }
        }
    } else if (MODE == 1 || MODE == 3) {
        // RoPE: head-local pairs (d, d+32) are nt'=0..3 and nt'+4 per head half
#pragma unroll
        for (int mt = 0; mt < 2; mt++) {
#pragma unroll
            for (int ri = 0; ri < 2; ri++) {
                int row = m0 + warp_m * 32 + mt * 16 + g + ri * 8;
                int t = row & (T_ - 1);
#pragma unroll
                for (int hh = 0; hh < 2; hh++) {
#pragma unroll
                    for (int ntp = 0; ntp < 4; ntp++) {
                        int nt = hh * 8 + ntp;
                        int d = ntp * 8 + t2 * 2;                  // < 32
                        float2 cc = *(const float2*)(cosp + t * HD_ + d);
                        float2 ss = *(const float2*)(sinp + t * HD_ + d);
                        float v0 = acc[mt][nt][ri * 2],     v1 = acc[mt][nt][ri * 2 + 1];
                        float w0 = acc[mt][nt + 4][ri * 2], w1 = acc[mt][nt + 4][ri * 2 + 1];
                        float q0 = (v0 * cc.x - w0 * ss.x) * qscale;
                        float q1 = (v1 * cc.y - w1 * ss.y) * qscale;
                        float p0 = (w0 * cc.x + v0 * ss.x) * qscale;
                        float p1 = (w1 * cc.y + v1 * ss.y) * qscale;
                        int col = n0 + warp_n * 128 + hh * 64 + d;
                        if (MODE == 1) {
                            uint32_t hp, lp;
                            split_pack2(q0, q1, hp, lp);
                            *(uint32_t*)(Ch + (size_t)row * D_ + col) = hp;
                            *(uint32_t*)(Cl + (size_t)row * D_ + col) = lp;
                            split_pack2(p0, p1, hp, lp);
                            *(uint32_t*)(Ch + (size_t)row * D_ + col + 32) = hp;
                            *(uint32_t*)(Cl + (size_t)row * D_ + col + 32) = lp;
                        } else {
                            *(uint32_t*)(Ch + (size_t)row * D_ + col)      = pack2h(q0, q1);
                            *(uint32_t*)(Ch + (size_t)row * D_ + col + 32) = pack2h(p0, p1);
                        }
                    }
                }
            }
        }
    } else {   // MODE 2: hi only
#pragma unroll
        for (int mt = 0; mt < 2; mt++) {
#pragma unroll
            for (int ri = 0; ri < 2; ri++) {
                int row = m0 + warp_m * 32 + mt * 16 + g + ri * 8;
#pragma unroll
                for (int nt = 0; nt < 16; nt++) {
                    int col = n0 + warp_n * 128 + nt * 8 + t2 * 2;
                    *(uint32_t*)(Ch + (size_t)row * D_ + col) =
                        pack2h(acc[mt][nt][ri * 2], acc[mt][nt][ri * 2 + 1]);
                }
            }
        }
    }
}

__global__ void __launch_bounds__(256)
gemm_qkv_mma(const float* __restrict__ cosp, const float* __restrict__ sinp)
{
    const int z = blockIdx.z;
    if (z == 0)
        gemm_core<1>(g_xh, g_xl, g_wh, nullptr, g_qh, g_ql, cosp, sinp, 0.125f);
    else if (z == 1)
        gemm_core<3>(g_xh, g_xl, g_wh + DD_, nullptr, g_kh, nullptr, cosp, sinp, 1.0f);
    else
        gemm_core<2>(g_xh, g_xl, g_wh + 2 * (size_t)DD_, nullptr, g_vh, nullptr,
                     nullptr, nullptr, 1.0f);
}

__global__ void __launch_bounds__(256)
gemm_out_mma(float* __restrict__ out)
{
    gemm_core<0>(g_aoh, g_aol, g_wh + 3 * (size_t)DD_, out, nullptr, nullptr,
                 nullptr, nullptr, 1.0f);
}

// ---------------------------------------------------------------------------
// Flash attention on mma.sync, fp16 2-pass (Q and P carry hi/lo; K,V hi only).
// CTA: 8 warps, Br=128 (16 rows/warp), Bc=64, Hd=64, double-buffered K/V.
// ---------------------------------------------------------------------------
#define FS    72                        // smem row stride in halfwords (144 B)
#define QH_E  0
#define QL_E  (128 * FS)                // 9216
#define KV_E  (2 * 128 * FS)            // 18432
#define ARR_E (64 * FS)                 // 4608
#define STG_E (2 * ARR_E)               // 9216 (kh, vh)
#define FA_BYTES ((KV_E + 2 * STG_E) * 2)   // 73728

__global__ void __launch_bounds__(256)
flash_mma()
{
    extern __shared__ __align__(128) char fsmc[];
    const uint32_t sb = smem_u32(fsmc);
    const int tid = threadIdx.x, lane = tid & 31, wid = tid >> 5;
    const int qt = gridDim.x - 1 - blockIdx.x;        // heavy tiles first
    const int bh = blockIdx.y;
    const int b = bh >> 4, h = bh & 15;
    const int g = lane >> 2, t2 = lane & 3;
    const size_t qtok = (size_t)b * T_ + (size_t)qt * 128;

    // --- issue Q loads (hi+lo) ---
#pragma unroll
    for (int i = 0; i < 8; i++) {
        int v = tid + i * 256;                 // 0..2047
        int arr = v >> 10, rem = v & 1023;
        int row = rem >> 3, c = rem & 7;
        const __half* src = arr ? g_ql : g_qh;
        cp16(sb + (uint32_t)((arr ? QL_E : QH_E) + row * FS + c * 8) * 2,
             src + (qtok + row) * D_ + h * 64 + c * 8);
    }

    auto issueKV = [&](int kt, int st) {
        const size_t tok = (size_t)b * T_ + (size_t)kt * 64;
#pragma unroll
        for (int i = 0; i < 4; i++) {
            int v = tid + i * 256;             // 0..1023
            int arr = v >> 9, rem = v & 511;   // 0: kh, 1: vh
            int row = rem >> 3, c = rem & 7;
            cp16(sb + (uint32_t)(KV_E + st * STG_E + arr * ARR_E + row * FS + c * 8) * 2,
                 (arr ? g_vh : g_kh) + (tok + row) * D_ + h * 64 + c * 8);
        }
        CP_COMMIT();
    };

    issueKV(0, 0);
    CP_WAIT(0);
    __syncthreads();

    // --- Q fragments into registers ---
    uint32_t qh[4][4], ql[4][4];
    {
        uint32_t base_r = (uint32_t)((wid * 16 + (lane & 15)) * FS + ((lane >> 4) & 1) * 8);
#pragma unroll
        for (int kg = 0; kg < 4; kg++) {
            ldsm4(qh[kg][0], qh[kg][1], qh[kg][2], qh[kg][3],
                  sb + (QH_E + base_r + kg * 16) * 2);
            ldsm4(ql[kg][0], ql[kg][1], ql[kg][2], ql[kg][3],
                  sb + (QL_E + base_r + kg * 16) * 2);
        }
    }

    float o[8][4];
#pragma unroll
    for (int nt = 0; nt < 8; nt++)
#pragma unroll
        for (int j = 0; j < 4; j++) o[nt][j] = 0.f;
    float m0r = -INFINITY, m1r = -INFINITY, l0 = 0.f, l1 = 0.f;

    const int nkt = 2 * qt + 2;
    const int row0 = qt * 128 + wid * 16 + g;

    for (int kt = 0; kt < nkt; kt++) {
        if (kt + 1 < nkt) issueKV(kt + 1, (kt + 1) & 1);

        const uint32_t kb_h = sb + (uint32_t)(KV_E + (kt & 1) * STG_E) * 2;
        const uint32_t vb_h = kb_h + ARR_E * 2;

        // ---- S = Q K^T (2-pass) ----
        float s[8][4];
#pragma unroll
        for (int nt = 0; nt < 8; nt++)
#pragma unroll
            for (int j = 0; j < 4; j++) s[nt][j] = 0.f;

#pragma unroll
        for (int kg = 0; kg < 4; kg++) {
            const uint32_t brow = (uint32_t)(((lane & 7) + ((lane >> 4) & 1) * 8) * FS
                                             + kg * 16 + ((lane >> 3) & 1) * 8) * 2;
#pragma unroll
            for (int pt = 0; pt < 4; pt++) {
                uint32_t k0, k1, k2, k3;
                ldsm4(k0, k1, k2, k3, kb_h + brow + (uint32_t)(pt * 16 * FS) * 2);
                mma16816(s[2 * pt],     qh[kg][0], qh[kg][1], qh[kg][2], qh[kg][3], k0, k1);
                mma16816(s[2 * pt],     ql[kg][0], ql[kg][1], ql[kg][2], ql[kg][3], k0, k1);
                mma16816(s[2 * pt + 1], qh[kg][0], qh[kg][1], qh[kg][2], qh[kg][3], k2, k3);
                mma16816(s[2 * pt + 1], ql[kg][0], ql[kg][1], ql[kg][2], ql[kg][3], k2, k3);
            }
        }

        // ---- causal mask ----
        if (kt * 64 + 63 > qt * 128 + wid * 16) {
#pragma unroll
            for (int nt = 0; nt < 8; nt++) {
#pragma unroll
                for (int j = 0; j < 4; j++) {
                    int col = kt * 64 + nt * 8 + t2 * 2 + (j & 1);
                    int row = row0 + (j >> 1) * 8;
                    if (col > row) s[nt][j] = -1e30f;
                }
            }
        }

        // ---- online softmax ----
        float mx0 = -INFINITY, mx1 = -INFINITY;
#pragma unroll
        for (int nt = 0; nt < 8; nt++) {
            mx0 = fmaxf(mx0, fmaxf(s[nt][0], s[nt][1]));
            mx1 = fmaxf(mx1, fmaxf(s[nt][2], s[nt][3]));
        }
        mx0 = fmaxf(mx0, __shfl_xor_sync(0xffffffffu, mx0, 1));
        mx0 = fmaxf(mx0, __shfl_xor_sync(0xffffffffu, mx0, 2));
        mx1 = fmaxf(mx1, __shfl_xor_sync(0xffffffffu, mx1, 1));
        mx1 = fmaxf(mx1, __shfl_xor_sync(0xffffffffu, mx1, 2));

        float mn0 = fmaxf(m0r, mx0), mn1 = fmaxf(m1r, mx1);
        float al0 = __expf(m0r - mn0), al1 = __expf(m1r - mn1);
        m0r = mn0; m1r = mn1;

        float su0 = 0.f, su1 = 0.f;
#pragma unroll
        for (int nt = 0; nt < 8; nt++) {
            s[nt][0] = __expf(s[nt][0] - mn0);
            s[nt][1] = __expf(s[nt][1] - mn0);
            s[nt][2] = __expf(s[nt][2] - mn1);
            s[nt][3] = __expf(s[nt][3] - mn1);
            su0 += s[nt][0] + s[nt][1];
            su1 += s[nt][2] + s[nt][3];
        }
        su0 += __shfl_xor_sync(0xffffffffu, su0, 1);
        su0 += __shfl_xor_sync(0xffffffffu, su0, 2);
        su1 += __shfl_xor_sync(0xffffffffu, su1, 1);
        su1 += __shfl_xor_sync(0xffffffffu, su1, 2);
        l0 = l0 * al0 + su0;
        l1 = l1 * al1 + su1;

#pragma unroll
        for (int nt = 0; nt < 8; nt++) {
            o[nt][0] *= al0; o[nt][1] *= al0;
            o[nt][2] *= al1; o[nt][3] *= al1;
        }

        // ---- O += P V (2-pass; P repacked hi/lo from S fragments) ----
#pragma unroll
        for (int kk = 0; kk < 4; kk++) {
            uint32_t pah[4], pal[4];
            split_pack2(s[2 * kk][0],     s[2 * kk][1],     pah[0], pal[0]);
            split_pack2(s[2 * kk][2],     s[2 * kk][3],     pah[1], pal[1]);
            split_pack2(s[2 * kk + 1][0], s[2 * kk + 1][1], pah[2], pal[2]);
            split_pack2(s[2 * kk + 1][2], s[2 * kk + 1][3], pah[3], pal[3]);

            const uint32_t vrow = (uint32_t)((kk * 16 + (lane & 7) + ((lane >> 3) & 1) * 8) * FS
                                             + ((lane >> 4) & 1) * 8) * 2;
#pragma unroll
            for (int dg = 0; dg < 4; dg++) {
                uint32_t v0, v1, v2, v3;
                ldsm4t(v0, v1, v2, v3, vb_h + vrow + (uint32_t)(dg * 16) * 2);
                mma16816(o[2 * dg],     pah[0], pah[1], pah[2], pah[3], v0, v1);
                mma16816(o[2 * dg],     pal[0], pal[1], pal[2], pal[3], v0, v1);
                mma16816(o[2 * dg + 1], pah[0], pah[1], pah[2], pah[3], v2, v3);
                mma16816(o[2 * dg + 1], pal[0], pal[1], pal[2], pal[3], v2, v3);
            }
        }

        if (kt + 1 < nkt) CP_WAIT(0);
        __syncthreads();
    }

    // ---- epilogue: normalize, split hi/lo, store ----
    const float inv0 = 1.0f / l0, inv1 = 1.0f / l1;
    const size_t tok0 = qtok + (size_t)(wid * 16 + g);
#pragma unroll
    for (int nt = 0; nt < 8; nt++) {
        int col = h * 64 + nt * 8 + t2 * 2;
        uint32_t hp, lp;
        split_pack2(o[nt][0] * inv0, o[nt][1] * inv0, hp, lp);
        *(uint32_t*)(g_aoh + tok0 * D_ + col) = hp;
        *(uint32_t*)(g_aol + tok0 * D_ + col) = lp;
        split_pack2(o[nt][2] * inv1, o[nt][3] * inv1, hp, lp);
        *(uint32_t*)(g_aoh + (tok0 + 8) * D_ + col) = hp;
        *(uint32_t*)(g_aol + (tok0 + 8) * D_ + col) = lp;
    }
}

// ---------------------------------------------------------------------------
// Harness entry
// ---------------------------------------------------------------------------
extern "C" void kernel_launch(void* const* d_in, const int* in_sizes, int n_in,
                              void* d_out, int out_size)
{
    const float* x    = (const float*)d_in[0];
    const float* cosp = (const float*)d_in[1];
    const float* sinp = (const float*)d_in[2];
    const float* wq   = (const float*)d_in[3];
    const float* wk   = (const float*)d_in[4];
    const float* wv   = (const float*)d_in[5];
    const float* wo   = (const float*)d_in[6];
    float* out        = (float*)d_out;

    cudaFuncSetAttribute(gemm_qkv_mma,
                         cudaFuncAttributeMaxDynamicSharedMemorySize, GEMM_SMEM_B);
    cudaFuncSetAttribute(gemm_out_mma,
                         cudaFuncAttributeMaxDynamicSharedMemorySize, GEMM_SMEM_B);
    cudaFuncSetAttribute(flash_mma,
                         cudaFuncAttributeMaxDynamicSharedMemorySize, FA_BYTES);

    // 0) fp32 -> fp16 conversions (x hi/lo, weights hi only)
    {
        int n2x = (M_TOT * D_) / 2;
        split_x_kernel<<<(n2x + 255) / 256, 256>>>(x);
        dim3 wg(DD_ / 2 / 256, 4);
        split_w4_kernel<<<wg, 256>>>(wq, wk, wv, wo);
    }

    // 1) QKV projections with fused RoPE/scale/convert epilogues
    {
        dim3 grid(D_ / 256, M_TOT / 128, 3);
        gemm_qkv_mma<<<grid, 256, GEMM_SMEM_B>>>(cosp, sinp);
    }

    // 2) Causal flash attention -> g_aoh/g_aol
    {
        dim3 grid(T_ / 128, B_ * H_);
        flash_mma<<<grid, 256, FA_BYTES>>>();
    }

    // 3) Output projection
    {
        dim3 grid(D_ / 256, M_TOT / 128, 1);
        gemm_out_mma<<<grid, 256, GEMM_SMEM_B>>>(out);
    }
}

// round 7
// speedup vs baseline: 1.7036x; 1.7036x over previous
#include <cuda_runtime.h>
#include <cuda_fp16.h>
#include <math.h>
#include <stdint.h>

// Problem dims (fixed by the reference)
#define B_   4
#define T_   2048
#define D_   1024
#define H_   16
#define HD_  64
#define M_TOT (B_*T_)   // 8192
#define DD_  (D_*D_)

// ---------------------------------------------------------------------------
// Device-global scratch (allocation-free rule). fp16; hi/lo only on A-side.
// ---------------------------------------------------------------------------
__device__ __align__(128) __half g_xh [M_TOT * D_];
__device__ __align__(128) __half g_xl [M_TOT * D_];
__device__ __align__(128) __half g_qh [M_TOT * D_];
__device__ __align__(128) __half g_ql [M_TOT * D_];
__device__ __align__(128) __half g_kh [M_TOT * D_];
__device__ __align__(128) __half g_vh [M_TOT * D_];
__device__ __align__(128) __half g_aoh[M_TOT * D_];
__device__ __align__(128) __half g_aol[M_TOT * D_];
__device__ __align__(128) __half g_wh [4 * DD_];   // q,k,v,o (hi only)

// ---------------------------------------------------------------------------
// PTX helpers (target-independent, sm_80-era)
// ---------------------------------------------------------------------------
__device__ __forceinline__ uint32_t smem_u32(const void* p) {
    uint32_t a;
    asm("{ .reg .u64 t; cvta.to.shared.u64 t, %1; cvt.u32.u64 %0, t; }"
        : "=r"(a) : "l"(p));
    return a;
}

__device__ __forceinline__ void cp16(uint32_t dst, const void* src) {
    asm volatile("cp.async.cg.shared.global [%0], [%1], 16;"
                 :: "r"(dst), "l"(src));
}
#define CP_COMMIT() asm volatile("cp.async.commit_group;" ::: "memory")
#define CP_WAIT(n)  asm volatile("cp.async.wait_group %0;" :: "n"(n) : "memory")

__device__ __forceinline__ void ldsm4(uint32_t& r0, uint32_t& r1,
                                      uint32_t& r2, uint32_t& r3, uint32_t a) {
    asm volatile("ldmatrix.sync.aligned.m8n8.x4.shared.b16 {%0,%1,%2,%3}, [%4];"
                 : "=r"(r0), "=r"(r1), "=r"(r2), "=r"(r3) : "r"(a));
}
__device__ __forceinline__ void ldsm4t(uint32_t& r0, uint32_t& r1,
                                       uint32_t& r2, uint32_t& r3, uint32_t a) {
    asm volatile("ldmatrix.sync.aligned.m8n8.x4.trans.shared.b16 {%0,%1,%2,%3}, [%4];"
                 : "=r"(r0), "=r"(r1), "=r"(r2), "=r"(r3) : "r"(a));
}

__device__ __forceinline__ void mma16816(float* c,
                                         uint32_t a0, uint32_t a1,
                                         uint32_t a2, uint32_t a3,
                                         uint32_t b0, uint32_t b1) {
    asm volatile("mma.sync.aligned.m16n8k16.row.col.f32.f16.f16.f32 "
                 "{%0,%1,%2,%3}, {%4,%5,%6,%7}, {%8,%9}, {%0,%1,%2,%3};"
                 : "+f"(c[0]), "+f"(c[1]), "+f"(c[2]), "+f"(c[3])
                 : "r"(a0), "r"(a1), "r"(a2), "r"(a3), "r"(b0), "r"(b1));
}

// fp32 pair -> packed fp16 hi pair + lo pair
__device__ __forceinline__ void split_pack2(float x, float y,
                                            uint32_t& hp, uint32_t& lp) {
    __half hx = __float2half(x);
    __half hy = __float2half(y);
    __half lx = __float2half(x - __half2float(hx));
    __half ly = __float2half(y - __half2float(hy));
    hp = (uint32_t)__half_as_ushort(hx) | ((uint32_t)__half_as_ushort(hy) << 16);
    lp = (uint32_t)__half_as_ushort(lx) | ((uint32_t)__half_as_ushort(ly) << 16);
}
__device__ __forceinline__ uint32_t pack2h(float x, float y) {
    return (uint32_t)__half_as_ushort(__float2half(x)) |
           ((uint32_t)__half_as_ushort(__float2half(y)) << 16);
}

// ---------------------------------------------------------------------------
// Input conversion kernels
// ---------------------------------------------------------------------------
__global__ void __launch_bounds__(256)
split_x_kernel(const float* __restrict__ src)
{
    int i = blockIdx.x * 256 + threadIdx.x;
    if (i >= M_TOT * D_ / 2) return;
    float2 a = ((const float2*)src)[i];
    uint32_t hp, lp;
    split_pack2(a.x, a.y, hp, lp);
    ((uint32_t*)g_xh)[i] = hp;
    ((uint32_t*)g_xl)[i] = lp;
}

__global__ void __launch_bounds__(256)
split_w4_kernel(const float* __restrict__ wq, const float* __restrict__ wk,
                const float* __restrict__ wv, const float* __restrict__ wo)
{
    int i = blockIdx.x * 256 + threadIdx.x;           // < DD_/2 exactly
    const float* srcs[4] = { wq, wk, wv, wo };
    float2 a = ((const float2*)srcs[blockIdx.y])[i];
    ((uint32_t*)(g_wh + (size_t)blockIdx.y * DD_))[i] = pack2h(a.x, a.y);
}

// ---------------------------------------------------------------------------
// fp16 2-pass GEMM: C[M,N] = (Ah+Al)[M,K] * Wh[N,K]^T
// CTA tile 128x128, BK=32, 8 warps (4m x 2n), 2-stage cp.async pipeline.
// MODE 0: fp32 out. 1: RoPE+scale hi/lo. 2: hi only. 3: RoPE hi only.
// ---------------------------------------------------------------------------
#define ROWB 40                         // smem row stride in halfwords (80 B)
#define S_AH 0
#define S_AL (128 * ROWB)               // 5120 h
#define S_BH (256 * ROWB)               // 10240 h
#define STAGE_E (384 * ROWB)            // 15360 h
#define STAGE_B (STAGE_E * 2)           // 30720 B
#define GEMM_SMEM_B (2 * STAGE_B)       // 61440 B

template <int MODE>
__device__ void gemm_core(const __half* __restrict__ Ah,
                          const __half* __restrict__ Al,
                          const __half* __restrict__ Bh,
                          float* __restrict__ Cf,
                          __half* __restrict__ Ch,
                          __half* __restrict__ Cl,
                          const float* __restrict__ cosp,
                          const float* __restrict__ sinp,
                          float qscale)
{
    extern __shared__ __align__(128) char smem[];
    const uint32_t sb = smem_u32(smem);
    const int tid  = threadIdx.x;
    const int lane = tid & 31;
    const int wid  = tid >> 5;
    const int warp_m = wid & 3;         // 32 rows
    const int warp_n = wid >> 2;        // 64 cols
    const int m0 = blockIdx.y * 128;
    const int n0 = blockIdx.x * 128;

    const int a_row = lane & 15;
    const int a_col = (lane >> 4) << 3;
    const int b_row = (lane & 7) + ((lane >> 4) << 3);
    const int b_col = ((lane >> 3) & 1) << 3;

    float acc[2][8][4];
#pragma unroll
    for (int mt = 0; mt < 2; mt++)
#pragma unroll
        for (int nt = 0; nt < 8; nt++)
#pragma unroll
            for (int r = 0; r < 4; r++) acc[mt][nt][r] = 0.f;

    auto issue = [&](int st, int k0) {
        const uint32_t dstb = sb + st * STAGE_B;
#pragma unroll
        for (int i = 0; i < 6; i++) {
            int v = (tid + (i & 1) * 256);              // 0..511
            int r = v >> 2, c = v & 3;
            if (i < 2)
                cp16(dstb + (uint32_t)(S_AH + r * ROWB + c * 8) * 2,
                     Ah + (size_t)(m0 + r) * D_ + k0 + c * 8);
            else if (i < 4)
                cp16(dstb + (uint32_t)(S_AL + r * ROWB + c * 8) * 2,
                     Al + (size_t)(m0 + r) * D_ + k0 + c * 8);
            else
                cp16(dstb + (uint32_t)(S_BH + r * ROWB + c * 8) * 2,
                     Bh + (size_t)(n0 + r) * D_ + k0 + c * 8);
        }
        CP_COMMIT();
    };

    const int NIT = D_ / 32;                // 32
    issue(0, 0);
    for (int ic = 0; ic < NIT; ic++) {
        if (ic + 1 < NIT) {
            issue((ic + 1) & 1, (ic + 1) * 32);
            CP_WAIT(1);
        } else {
            CP_WAIT(0);
        }
        __syncthreads();

        const uint32_t sa = sb + (ic & 1) * STAGE_B;
#pragma unroll
        for (int ks = 0; ks < 2; ks++) {
            uint32_t ah[2][4], al_[2][4];
#pragma unroll
            for (int mt = 0; mt < 2; mt++) {
                uint32_t ra = sa + (uint32_t)((warp_m * 32 + mt * 16 + a_row) * ROWB
                                              + ks * 16 + a_col) * 2;
                ldsm4(ah[mt][0],  ah[mt][1],  ah[mt][2],  ah[mt][3],  ra + S_AH * 2);
                ldsm4(al_[mt][0], al_[mt][1], al_[mt][2], al_[mt][3], ra + S_AL * 2);
            }
#pragma unroll
            for (int pt = 0; pt < 4; pt++) {
                uint32_t b0, b1, b2, b3;
                uint32_t rb = sa + (uint32_t)(S_BH + (warp_n * 64 + pt * 16 + b_row) * ROWB
                                              + ks * 16 + b_col) * 2;
                ldsm4(b0, b1, b2, b3, rb);
#pragma unroll
                for (int mt = 0; mt < 2; mt++) {
                    mma16816(acc[mt][2 * pt],     ah[mt][0],  ah[mt][1],  ah[mt][2],  ah[mt][3],  b0, b1);
                    mma16816(acc[mt][2 * pt],     al_[mt][0], al_[mt][1], al_[mt][2], al_[mt][3], b0, b1);
                    mma16816(acc[mt][2 * pt + 1], ah[mt][0],  ah[mt][1],  ah[mt][2],  ah[mt][3],  b2, b3);
                    mma16816(acc[mt][2 * pt + 1], al_[mt][0], al_[mt][1], al_[mt][2], al_[mt][3], b2, b3);
                }
            }
        }
        __syncthreads();
    }

    const int g = lane >> 2, t2 = lane & 3;
    if (MODE == 0) {
#pragma unroll
        for (int mt = 0; mt < 2; mt++) {
            int r0 = m0 + warp_m * 32 + mt * 16 + g;
#pragma unroll
            for (int nt = 0; nt < 8; nt++) {
                int col = n0 + warp_n * 64 + nt * 8 + t2 * 2;
                *(float2*)(Cf + (size_t)r0 * D_ + col) =
                    make_float2(acc[mt][nt][0], acc[mt][nt][1]);
                *(float2*)(Cf + (size_t)(r0 + 8) * D_ + col) =
                    make_float2(acc[mt][nt][2], acc[mt][nt][3]);
            }
        }
    } else if (MODE == 1 || MODE == 3) {
        // RoPE: head-local pairs (d, d+32) live in nt and nt+4 (warp_n*64 = head half)
#pragma unroll
        for (int mt = 0; mt < 2; mt++) {
#pragma unroll
            for (int ri = 0; ri < 2; ri++) {
                int row = m0 + warp_m * 32 + mt * 16 + g + ri * 8;
                int t = row & (T_ - 1);
#pragma unroll
                for (int nt = 0; nt < 4; nt++) {
                    int d = nt * 8 + t2 * 2;                  // < 32
                    float2 cc = *(const float2*)(cosp + t * HD_ + d);
                    float2 ss = *(const float2*)(sinp + t * HD_ + d);
                    float v0 = acc[mt][nt][ri * 2],     v1 = acc[mt][nt][ri * 2 + 1];
                    float w0 = acc[mt][nt + 4][ri * 2], w1 = acc[mt][nt + 4][ri * 2 + 1];
                    float q0 = (v0 * cc.x - w0 * ss.x) * qscale;
                    float q1 = (v1 * cc.y - w1 * ss.y) * qscale;
                    float p0 = (w0 * cc.x + v0 * ss.x) * qscale;
                    float p1 = (w1 * cc.y + v1 * ss.y) * qscale;
                    int col = n0 + warp_n * 64 + d;
                    if (MODE == 1) {
                        uint32_t hp, lp;
                        split_pack2(q0, q1, hp, lp);
                        *(uint32_t*)(Ch + (size_t)row * D_ + col) = hp;
                        *(uint32_t*)(Cl + (size_t)row * D_ + col) = lp;
                        split_pack2(p0, p1, hp, lp);
                        *(uint32_t*)(Ch + (size_t)row * D_ + col + 32) = hp;
                        *(uint32_t*)(Cl + (size_t)row * D_ + col + 32) = lp;
                    } else {
                        *(uint32_t*)(Ch + (size_t)row * D_ + col)      = pack2h(q0, q1);
                        *(uint32_t*)(Ch + (size_t)row * D_ + col + 32) = pack2h(p0, p1);
                    }
                }
            }
        }
    } else {   // MODE 2: hi only
#pragma unroll
        for (int mt = 0; mt < 2; mt++) {
#pragma unroll
            for (int ri = 0; ri < 2; ri++) {
                int row = m0 + warp_m * 32 + mt * 16 + g + ri * 8;
#pragma unroll
                for (int nt = 0; nt < 8; nt++) {
                    int col = n0 + warp_n * 64 + nt * 8 + t2 * 2;
                    *(uint32_t*)(Ch + (size_t)row * D_ + col) =
                        pack2h(acc[mt][nt][ri * 2], acc[mt][nt][ri * 2 + 1]);
                }
            }
        }
    }
}

__global__ void __launch_bounds__(256, 2)
gemm_qkv_mma(const float* __restrict__ cosp, const float* __restrict__ sinp)
{
    const int z = blockIdx.z;
    if (z == 0)
        gemm_core<1>(g_xh, g_xl, g_wh, nullptr, g_qh, g_ql, cosp, sinp, 0.125f);
    else if (z == 1)
        gemm_core<3>(g_xh, g_xl, g_wh + DD_, nullptr, g_kh, nullptr, cosp, sinp, 1.0f);
    else
        gemm_core<2>(g_xh, g_xl, g_wh + 2 * (size_t)DD_, nullptr, g_vh, nullptr,
                     nullptr, nullptr, 1.0f);
}

__global__ void __launch_bounds__(256, 2)
gemm_out_mma(float* __restrict__ out)
{
    gemm_core<0>(g_aoh, g_aol, g_wh + 3 * (size_t)DD_, out, nullptr, nullptr,
                 nullptr, nullptr, 1.0f);
}

// ---------------------------------------------------------------------------
// Flash attention on mma.sync, fp16 2-pass (Q and P carry hi/lo; K,V hi only).
// CTA: 8 warps, Br=128 (16 rows/warp), Bc=64, Hd=64, double-buffered K/V.
// __launch_bounds__(256,2): cap regs at 128 so 2 CTAs/SM co-reside.
// ---------------------------------------------------------------------------
#define FS    72                        // smem row stride in halfwords (144 B)
#define QH_E  0
#define QL_E  (128 * FS)                // 9216
#define KV_E  (2 * 128 * FS)            // 18432
#define ARR_E (64 * FS)                 // 4608
#define STG_E (2 * ARR_E)               // 9216 (kh, vh)
#define FA_BYTES ((KV_E + 2 * STG_E) * 2)   // 73728

__global__ void __launch_bounds__(256, 2)
flash_mma()
{
    extern __shared__ __align__(128) char fsmc[];
    const uint32_t sb = smem_u32(fsmc);
    const int tid = threadIdx.x, lane = tid & 31, wid = tid >> 5;
    const int qt = gridDim.x - 1 - blockIdx.x;        // heavy tiles first
    const int bh = blockIdx.y;
    const int b = bh >> 4, h = bh & 15;
    const int g = lane >> 2, t2 = lane & 3;
    const size_t qtok = (size_t)b * T_ + (size_t)qt * 128;

    // --- issue Q loads (hi+lo) ---
#pragma unroll
    for (int i = 0; i < 8; i++) {
        int v = tid + i * 256;                 // 0..2047
        int arr = v >> 10, rem = v & 1023;
        int row = rem >> 3, c = rem & 7;
        const __half* src = arr ? g_ql : g_qh;
        cp16(sb + (uint32_t)((arr ? QL_E : QH_E) + row * FS + c * 8) * 2,
             src + (qtok + row) * D_ + h * 64 + c * 8);
    }

    auto issueKV = [&](int kt, int st) {
        const size_t tok = (size_t)b * T_ + (size_t)kt * 64;
#pragma unroll
        for (int i = 0; i < 4; i++) {
            int v = tid + i * 256;             // 0..1023
            int arr = v >> 9, rem = v & 511;   // 0: kh, 1: vh
            int row = rem >> 3, c = rem & 7;
            cp16(sb + (uint32_t)(KV_E + st * STG_E + arr * ARR_E + row * FS + c * 8) * 2,
                 (arr ? g_vh : g_kh) + (tok + row) * D_ + h * 64 + c * 8);
        }
        CP_COMMIT();
    };

    issueKV(0, 0);
    CP_WAIT(0);
    __syncthreads();

    // --- Q fragments into registers ---
    uint32_t qh[4][4], ql[4][4];
    {
        uint32_t base_r = (uint32_t)((wid * 16 + (lane & 15)) * FS + ((lane >> 4) & 1) * 8);
#pragma unroll
        for (int kg = 0; kg < 4; kg++) {
            ldsm4(qh[kg][0], qh[kg][1], qh[kg][2], qh[kg][3],
                  sb + (QH_E + base_r + kg * 16) * 2);
            ldsm4(ql[kg][0], ql[kg][1], ql[kg][2], ql[kg][3],
                  sb + (QL_E + base_r + kg * 16) * 2);
        }
    }

    float o[8][4];
#pragma unroll
    for (int nt = 0; nt < 8; nt++)
#pragma unroll
        for (int j = 0; j < 4; j++) o[nt][j] = 0.f;
    float m0r = -INFINITY, m1r = -INFINITY, l0 = 0.f, l1 = 0.f;

    const int nkt = 2 * qt + 2;
    const int row0 = qt * 128 + wid * 16 + g;

    for (int kt = 0; kt < nkt; kt++) {
        if (kt + 1 < nkt) issueKV(kt + 1, (kt + 1) & 1);

        const uint32_t kb_h = sb + (uint32_t)(KV_E + (kt & 1) * STG_E) * 2;
        const uint32_t vb_h = kb_h + ARR_E * 2;

        // ---- S = Q K^T (2-pass) ----
        float s[8][4];
#pragma unroll
        for (int nt = 0; nt < 8; nt++)
#pragma unroll
            for (int j = 0; j < 4; j++) s[nt][j] = 0.f;

#pragma unroll
        for (int kg = 0; kg < 4; kg++) {
            const uint32_t brow = (uint32_t)(((lane & 7) + ((lane >> 4) & 1) * 8) * FS
                                             + kg * 16 + ((lane >> 3) & 1) * 8) * 2;
#pragma unroll
            for (int pt = 0; pt < 4; pt++) {
                uint32_t k0, k1, k2, k3;
                ldsm4(k0, k1, k2, k3, kb_h + brow + (uint32_t)(pt * 16 * FS) * 2);
                mma16816(s[2 * pt],     qh[kg][0], qh[kg][1], qh[kg][2], qh[kg][3], k0, k1);
                mma16816(s[2 * pt],     ql[kg][0], ql[kg][1], ql[kg][2], ql[kg][3], k0, k1);
                mma16816(s[2 * pt + 1], qh[kg][0], qh[kg][1], qh[kg][2], qh[kg][3], k2, k3);
                mma16816(s[2 * pt + 1], ql[kg][0], ql[kg][1], ql[kg][2], ql[kg][3], k2, k3);
            }
        }

        // ---- causal mask ----
        if (kt * 64 + 63 > qt * 128 + wid * 16) {
#pragma unroll
            for (int nt = 0; nt < 8; nt++) {
#pragma unroll
                for (int j = 0; j < 4; j++) {
                    int col = kt * 64 + nt * 8 + t2 * 2 + (j & 1);
                    int row = row0 + (j >> 1) * 8;
                    if (col > row) s[nt][j] = -1e30f;
                }
            }
        }

        // ---- online softmax ----
        float mx0 = -INFINITY, mx1 = -INFINITY;
#pragma unroll
        for (int nt = 0; nt < 8; nt++) {
            mx0 = fmaxf(mx0, fmaxf(s[nt][0], s[nt][1]));
            mx1 = fmaxf(mx1, fmaxf(s[nt][2], s[nt][3]));
        }
        mx0 = fmaxf(mx0, __shfl_xor_sync(0xffffffffu, mx0, 1));
        mx0 = fmaxf(mx0, __shfl_xor_sync(0xffffffffu, mx0, 2));
        mx1 = fmaxf(mx1, __shfl_xor_sync(0xffffffffu, mx1, 1));
        mx1 = fmaxf(mx1, __shfl_xor_sync(0xffffffffu, mx1, 2));

        float mn0 = fmaxf(m0r, mx0), mn1 = fmaxf(m1r, mx1);
        float al0 = __expf(m0r - mn0), al1 = __expf(m1r - mn1);
        m0r = mn0; m1r = mn1;

        float su0 = 0.f, su1 = 0.f;
#pragma unroll
        for (int nt = 0; nt < 8; nt++) {
            s[nt][0] = __expf(s[nt][0] - mn0);
            s[nt][1] = __expf(s[nt][1] - mn0);
            s[nt][2] = __expf(s[nt][2] - mn1);
            s[nt][3] = __expf(s[nt][3] - mn1);
            su0 += s[nt][0] + s[nt][1];
            su1 += s[nt][2] + s[nt][3];
        }
        su0 += __shfl_xor_sync(0xffffffffu, su0, 1);
        su0 += __shfl_xor_sync(0xffffffffu, su0, 2);
        su1 += __shfl_xor_sync(0xffffffffu, su1, 1);
        su1 += __shfl_xor_sync(0xffffffffu, su1, 2);
        l0 = l0 * al0 + su0;
        l1 = l1 * al1 + su1;

#pragma unroll
        for (int nt = 0; nt < 8; nt++) {
            o[nt][0] *= al0; o[nt][1] *= al0;
            o[nt][2] *= al1; o[nt][3] *= al1;
        }

        // ---- O += P V (2-pass; P repacked hi/lo from S fragments) ----
#pragma unroll
        for (int kk = 0; kk < 4; kk++) {
            uint32_t pah[4], pal[4];
            split_pack2(s[2 * kk][0],     s[2 * kk][1],     pah[0], pal[0]);
            split_pack2(s[2 * kk][2],     s[2 * kk][3],     pah[1], pal[1]);
            split_pack2(s[2 * kk + 1][0], s[2 * kk + 1][1], pah[2], pal[2]);
            split_pack2(s[2 * kk + 1][2], s[2 * kk + 1][3], pah[3], pal[3]);

            const uint32_t vrow = (uint32_t)((kk * 16 + (lane & 7) + ((lane >> 3) & 1) * 8) * FS
                                             + ((lane >> 4) & 1) * 8) * 2;
#pragma unroll
            for (int dg = 0; dg < 4; dg++) {
                uint32_t v0, v1, v2, v3;
                ldsm4t(v0, v1, v2, v3, vb_h + vrow + (uint32_t)(dg * 16) * 2);
                mma16816(o[2 * dg],     pah[0], pah[1], pah[2], pah[3], v0, v1);
                mma16816(o[2 * dg],     pal[0], pal[1], pal[2], pal[3], v0, v1);
                mma16816(o[2 * dg + 1], pah[0], pah[1], pah[2], pah[3], v2, v3);
                mma16816(o[2 * dg + 1], pal[0], pal[1], pal[2], pal[3], v2, v3);
            }
        }

        if (kt + 1 < nkt) CP_WAIT(0);
        __syncthreads();
    }

    // ---- epilogue: normalize, split hi/lo, store ----
    const float inv0 = 1.0f / l0, inv1 = 1.0f / l1;
    const size_t tok0 = qtok + (size_t)(wid * 16 + g);
#pragma unroll
    for (int nt = 0; nt < 8; nt++) {
        int col = h * 64 + nt * 8 + t2 * 2;
        uint32_t hp, lp;
        split_pack2(o[nt][0] * inv0, o[nt][1] * inv0, hp, lp);
        *(uint32_t*)(g_aoh + tok0 * D_ + col) = hp;
        *(uint32_t*)(g_aol + tok0 * D_ + col) = lp;
        split_pack2(o[nt][2] * inv1, o[nt][3] * inv1, hp, lp);
        *(uint32_t*)(g_aoh + (tok0 + 8) * D_ + col) = hp;
        *(uint32_t*)(g_aol + (tok0 + 8) * D_ + col) = lp;
    }
}

// ---------------------------------------------------------------------------
// Harness entry
// ---------------------------------------------------------------------------
extern "C" void kernel_launch(void* const* d_in, const int* in_sizes, int n_in,
                              void* d_out, int out_size)
{
    const float* x    = (const float*)d_in[0];
    const float* cosp = (const float*)d_in[1];
    const float* sinp = (const float*)d_in[2];
    const float* wq   = (const float*)d_in[3];
    const float* wk   = (const float*)d_in[4];
    const float* wv   = (const float*)d_in[5];
    const float* wo   = (const float*)d_in[6];
    float* out        = (float*)d_out;

    cudaFuncSetAttribute(gemm_qkv_mma,
                         cudaFuncAttributeMaxDynamicSharedMemorySize, GEMM_SMEM_B);
    cudaFuncSetAttribute(gemm_out_mma,
                         cudaFuncAttributeMaxDynamicSharedMemorySize, GEMM_SMEM_B);
    cudaFuncSetAttribute(flash_mma,
                         cudaFuncAttributeMaxDynamicSharedMemorySize, FA_BYTES);

    // 0) fp32 -> fp16 conversions (x hi/lo, weights hi only)
    {
        int n2x = (M_TOT * D_) / 2;
        split_x_kernel<<<(n2x + 255) / 256, 256>>>(x);
        dim3 wg(DD_ / 2 / 256, 4);
        split_w4_kernel<<<wg, 256>>>(wq, wk, wv, wo);
    }

    // 1) QKV projections with fused RoPE/scale/convert epilogues
    {
        dim3 grid(D_ / 128, M_TOT / 128, 3);
        gemm_qkv_mma<<<grid, 256, GEMM_SMEM_B>>>(cosp, sinp);
    }

    // 2) Causal flash attention -> g_aoh/g_aol
    {
        dim3 grid(T_ / 128, B_ * H_);
        flash_mma<<<grid, 256, FA_BYTES>>>();
    }

    // 3) Output projection
    {
        dim3 grid(D_ / 128, M_TOT / 128, 1);
        gemm_out_mma<<<grid, 256, GEMM_SMEM_B>>>(out);
    }
}

// round 9
// speedup vs baseline: 2.2508x; 1.3212x over previous
#include <cuda_runtime.h>
#include <cuda_fp16.h>
#include <math.h>
#include <stdint.h>

// Problem dims (fixed by the reference)
#define B_   4
#define T_   2048
#define D_   1024
#define H_   16
#define HD_  64
#define M_TOT (B_*T_)   // 8192
#define DD_  (D_*D_)

// ---------------------------------------------------------------------------
// Device-global scratch (allocation-free rule). fp16; hi/lo only where needed.
// ---------------------------------------------------------------------------
__device__ __align__(128) __half g_xh [M_TOT * D_];
__device__ __align__(128) __half g_xl [M_TOT * D_];
__device__ __align__(128) __half g_qh [M_TOT * D_];
__device__ __align__(128) __half g_ql [M_TOT * D_];
__device__ __align__(128) __half g_kh [M_TOT * D_];
__device__ __align__(128) __half g_vh [M_TOT * D_];
__device__ __align__(128) __half g_aoh[M_TOT * D_];
__device__ __align__(128) __half g_wh [4 * DD_];   // q,k,v,o (hi only)

// ---------------------------------------------------------------------------
// PTX helpers (target-independent, sm_80-era)
// ---------------------------------------------------------------------------
__device__ __forceinline__ uint32_t smem_u32(const void* p) {
    uint32_t a;
    asm("{ .reg .u64 t; cvta.to.shared.u64 t, %1; cvt.u32.u64 %0, t; }"
        : "=r"(a) : "l"(p));
    return a;
}

__device__ __forceinline__ void cp16(uint32_t dst, const void* src) {
    asm volatile("cp.async.cg.shared.global [%0], [%1], 16;"
                 :: "r"(dst), "l"(src));
}
#define CP_COMMIT() asm volatile("cp.async.commit_group;" ::: "memory")
#define CP_WAIT(n)  asm volatile("cp.async.wait_group %0;" :: "n"(n) : "memory")

__device__ __forceinline__ void ldsm4(uint32_t& r0, uint32_t& r1,
                                      uint32_t& r2, uint32_t& r3, uint32_t a) {
    asm volatile("ldmatrix.sync.aligned.m8n8.x4.shared.b16 {%0,%1,%2,%3}, [%4];"
                 : "=r"(r0), "=r"(r1), "=r"(r2), "=r"(r3) : "r"(a));
}
__device__ __forceinline__ void ldsm4t(uint32_t& r0, uint32_t& r1,
                                       uint32_t& r2, uint32_t& r3, uint32_t a) {
    asm volatile("ldmatrix.sync.aligned.m8n8.x4.trans.shared.b16 {%0,%1,%2,%3}, [%4];"
                 : "=r"(r0), "=r"(r1), "=r"(r2), "=r"(r3) : "r"(a));
}

__device__ __forceinline__ void mma16816(float* c,
                                         uint32_t a0, uint32_t a1,
                                         uint32_t a2, uint32_t a3,
                                         uint32_t b0, uint32_t b1) {
    asm volatile("mma.sync.aligned.m16n8k16.row.col.f32.f16.f16.f32 "
                 "{%0,%1,%2,%3}, {%4,%5,%6,%7}, {%8,%9}, {%0,%1,%2,%3};"
                 : "+f"(c[0]), "+f"(c[1]), "+f"(c[2]), "+f"(c[3])
                 : "r"(a0), "r"(a1), "r"(a2), "r"(a3), "r"(b0), "r"(b1));
}

__device__ __forceinline__ float ex2f(float x) {
    float y;
    asm("ex2.approx.ftz.f32 %0, %1;" : "=f"(y) : "f"(x));
    return y;
}

// fp32 pair -> packed fp16 hi pair + lo pair
__device__ __forceinline__ void split_pack2(float x, float y,
                                            uint32_t& hp, uint32_t& lp) {
    __half hx = __float2half(x);
    __half hy = __float2half(y);
    __half lx = __float2half(x - __half2float(hx));
    __half ly = __float2half(y - __half2float(hy));
    hp = (uint32_t)__half_as_ushort(hx) | ((uint32_t)__half_as_ushort(hy) << 16);
    lp = (uint32_t)__half_as_ushort(lx) | ((uint32_t)__half_as_ushort(ly) << 16);
}
__device__ __forceinline__ uint32_t pack2h(float x, float y) {
    return (uint32_t)__half_as_ushort(__float2half(x)) |
           ((uint32_t)__half_as_ushort(__float2half(y)) << 16);
}

// ---------------------------------------------------------------------------
// Input conversion kernels
// ---------------------------------------------------------------------------
__global__ void __launch_bounds__(256)
split_x_kernel(const float* __restrict__ src)
{
    int i = blockIdx.x * 256 + threadIdx.x;
    if (i >= M_TOT * D_ / 2) return;
    float2 a = ((const float2*)src)[i];
    uint32_t hp, lp;
    split_pack2(a.x, a.y, hp, lp);
    ((uint32_t*)g_xh)[i] = hp;
    ((uint32_t*)g_xl)[i] = lp;
}

__global__ void __launch_bounds__(256)
split_w4_kernel(const float* __restrict__ wq, const float* __restrict__ wk,
                const float* __restrict__ wv, const float* __restrict__ wo)
{
    int i = blockIdx.x * 256 + threadIdx.x;           // < DD_/2 exactly
    const float* srcs[4] = { wq, wk, wv, wo };
    float2 a = ((const float2*)srcs[blockIdx.y])[i];
    ((uint32_t*)(g_wh + (size_t)blockIdx.y * DD_))[i] = pack2h(a.x, a.y);
}

// ---------------------------------------------------------------------------
// fp16 GEMM: C[M,N] = A[M,K] * W[N,K]^T ; NPASS=2 adds the A-lo pass.
// CTA tile 128x128, BK=32, 8 warps (4m x 2n), 2-stage cp.async pipeline.
// MODE 0: fp32 out. 1: RoPE+scale hi/lo. 2: hi only. 3: RoPE hi only.
// ---------------------------------------------------------------------------
#define ROWB 40                         // smem row stride in halfwords (80 B)
#define S_AH 0
#define S_AL (128 * ROWB)               // 5120 h
#define S_BH (256 * ROWB)               // 10240 h
#define STAGE_E (384 * ROWB)            // 15360 h
#define STAGE_B (STAGE_E * 2)           // 30720 B
#define GEMM_SMEM_B (2 * STAGE_B)       // 61440 B

template <int MODE, int NPASS>
__device__ void gemm_core(const __half* __restrict__ Ah,
                          const __half* __restrict__ Al,
                          const __half* __restrict__ Bh,
                          float* __restrict__ Cf,
                          __half* __restrict__ Ch,
                          __half* __restrict__ Cl,
                          const float* __restrict__ cosp,
                          const float* __restrict__ sinp,
                          float qscale)
{
    extern __shared__ __align__(128) char smem[];
    const uint32_t sb = smem_u32(smem);
    const int tid  = threadIdx.x;
    const int lane = tid & 31;
    const int wid  = tid >> 5;
    const int warp_m = wid & 3;         // 32 rows
    const int warp_n = wid >> 2;        // 64 cols
    const int m0 = blockIdx.y * 128;
    const int n0 = blockIdx.x * 128;

    const int a_row = lane & 15;
    const int a_col = (lane >> 4) << 3;
    const int b_row = (lane & 7) + ((lane >> 4) << 3);
    const int b_col = ((lane >> 3) & 1) << 3;

    float acc[2][8][4];
#pragma unroll
    for (int mt = 0; mt < 2; mt++)
#pragma unroll
        for (int nt = 0; nt < 8; nt++)
#pragma unroll
            for (int r = 0; r < 4; r++) acc[mt][nt][r] = 0.f;

    auto issue = [&](int st, int k0) {
        const uint32_t dstb = sb + st * STAGE_B;
#pragma unroll
        for (int i = 0; i < 6; i++) {
            if (NPASS == 1 && i >= 2 && i < 4) continue;
            int v = (tid + (i & 1) * 256);              // 0..511
            int r = v >> 2, c = v & 3;
            if (i < 2)
                cp16(dstb + (uint32_t)(S_AH + r * ROWB + c * 8) * 2,
                     Ah + (size_t)(m0 + r) * D_ + k0 + c * 8);
            else if (i < 4)
                cp16(dstb + (uint32_t)(S_AL + r * ROWB + c * 8) * 2,
                     Al + (size_t)(m0 + r) * D_ + k0 + c * 8);
            else
                cp16(dstb + (uint32_t)(S_BH + r * ROWB + c * 8) * 2,
                     Bh + (size_t)(n0 + r) * D_ + k0 + c * 8);
        }
        CP_COMMIT();
    };

    const int NIT = D_ / 32;                // 32
    issue(0, 0);
    for (int ic = 0; ic < NIT; ic++) {
        if (ic + 1 < NIT) {
            issue((ic + 1) & 1, (ic + 1) * 32);
            CP_WAIT(1);
        } else {
            CP_WAIT(0);
        }
        __syncthreads();

        const uint32_t sa = sb + (ic & 1) * STAGE_B;
#pragma unroll
        for (int ks = 0; ks < 2; ks++) {
            uint32_t ah[2][4], al_[2][4];
#pragma unroll
            for (int mt = 0; mt < 2; mt++) {
                uint32_t ra = sa + (uint32_t)((warp_m * 32 + mt * 16 + a_row) * ROWB
                                              + ks * 16 + a_col) * 2;
                ldsm4(ah[mt][0],  ah[mt][1],  ah[mt][2],  ah[mt][3],  ra + S_AH * 2);
                if (NPASS == 2)
                    ldsm4(al_[mt][0], al_[mt][1], al_[mt][2], al_[mt][3], ra + S_AL * 2);
            }
#pragma unroll
            for (int pt = 0; pt < 4; pt++) {
                uint32_t b0, b1, b2, b3;
                uint32_t rb = sa + (uint32_t)(S_BH + (warp_n * 64 + pt * 16 + b_row) * ROWB
                                              + ks * 16 + b_col) * 2;
                ldsm4(b0, b1, b2, b3, rb);
#pragma unroll
                for (int mt = 0; mt < 2; mt++) {
                    mma16816(acc[mt][2 * pt],     ah[mt][0],  ah[mt][1],  ah[mt][2],  ah[mt][3],  b0, b1);
                    mma16816(acc[mt][2 * pt + 1], ah[mt][0],  ah[mt][1],  ah[mt][2],  ah[mt][3],  b2, b3);
                    if (NPASS == 2) {
                        mma16816(acc[mt][2 * pt],     al_[mt][0], al_[mt][1], al_[mt][2], al_[mt][3], b0, b1);
                        mma16816(acc[mt][2 * pt + 1], al_[mt][0], al_[mt][1], al_[mt][2], al_[mt][3], b2, b3);
                    }
                }
            }
        }
        __syncthreads();
    }

    const int g = lane >> 2, t2 = lane & 3;
    if (MODE == 0) {
#pragma unroll
        for (int mt = 0; mt < 2; mt++) {
            int r0 = m0 + warp_m * 32 + mt * 16 + g;
#pragma unroll
            for (int nt = 0; nt < 8; nt++) {
                int col = n0 + warp_n * 64 + nt * 8 + t2 * 2;
                *(float2*)(Cf + (size_t)r0 * D_ + col) =
                    make_float2(acc[mt][nt][0], acc[mt][nt][1]);
                *(float2*)(Cf + (size_t)(r0 + 8) * D_ + col) =
                    make_float2(acc[mt][nt][2], acc[mt][nt][3]);
            }
        }
    } else if (MODE == 1 || MODE == 3) {
        // RoPE: head-local pairs (d, d+32) live in nt and nt+4 (warp_n*64 = head half)
#pragma unroll
        for (int mt = 0; mt < 2; mt++) {
#pragma unroll
            for (int ri = 0; ri < 2; ri++) {
                int row = m0 + warp_m * 32 + mt * 16 + g + ri * 8;
                int t = row & (T_ - 1);
#pragma unroll
                for (int nt = 0; nt < 4; nt++) {
                    int d = nt * 8 + t2 * 2;                  // < 32
                    float2 cc = *(const float2*)(cosp + t * HD_ + d);
                    float2 ss = *(const float2*)(sinp + t * HD_ + d);
                    float v0 = acc[mt][nt][ri * 2],     v1 = acc[mt][nt][ri * 2 + 1];
                    float w0 = acc[mt][nt + 4][ri * 2], w1 = acc[mt][nt + 4][ri * 2 + 1];
                    float q0 = (v0 * cc.x - w0 * ss.x) * qscale;
                    float q1 = (v1 * cc.y - w1 * ss.y) * qscale;
                    float p0 = (w0 * cc.x + v0 * ss.x) * qscale;
                    float p1 = (w1 * cc.y + v1 * ss.y) * qscale;
                    int col = n0 + warp_n * 64 + d;
                    if (MODE == 1) {
                        uint32_t hp, lp;
                        split_pack2(q0, q1, hp, lp);
                        *(uint32_t*)(Ch + (size_t)row * D_ + col) = hp;
                        *(uint32_t*)(Cl + (size_t)row * D_ + col) = lp;
                        split_pack2(p0, p1, hp, lp);
                        *(uint32_t*)(Ch + (size_t)row * D_ + col + 32) = hp;
                        *(uint32_t*)(Cl + (size_t)row * D_ + col + 32) = lp;
                    } else {
                        *(uint32_t*)(Ch + (size_t)row * D_ + col)      = pack2h(q0, q1);
                        *(uint32_t*)(Ch + (size_t)row * D_ + col + 32) = pack2h(p0, p1);
                    }
                }
            }
        }
    } else {   // MODE 2: hi only
#pragma unroll
        for (int mt = 0; mt < 2; mt++) {
#pragma unroll
            for (int ri = 0; ri < 2; ri++) {
                int row = m0 + warp_m * 32 + mt * 16 + g + ri * 8;
#pragma unroll
                for (int nt = 0; nt < 8; nt++) {
                    int col = n0 + warp_n * 64 + nt * 8 + t2 * 2;
                    *(uint32_t*)(Ch + (size_t)row * D_ + col) =
                        pack2h(acc[mt][nt][ri * 2], acc[mt][nt][ri * 2 + 1]);
                }
            }
        }
    }
}

// log2(e) folded into q so flash softmax can use raw ex2
#define QSCALE_LOG2E (0.125f * 1.44269504088896f)

__global__ void __launch_bounds__(256, 2)
gemm_qkv_mma(const float* __restrict__ cosp, const float* __restrict__ sinp)
{
    const int z = blockIdx.z;
    if (z == 0)
        gemm_core<1, 2>(g_xh, g_xl, g_wh, nullptr, g_qh, g_ql, cosp, sinp, QSCALE_LOG2E);
    else if (z == 1)
        gemm_core<3, 2>(g_xh, g_xl, g_wh + DD_, nullptr, g_kh, nullptr, cosp, sinp, 1.0f);
    else
        gemm_core<2, 1>(g_xh, nullptr, g_wh + 2 * (size_t)DD_, nullptr, g_vh, nullptr,
                        nullptr, nullptr, 1.0f);
}

__global__ void __launch_bounds__(256, 2)
gemm_out_mma(float* __restrict__ out)
{
    gemm_core<0, 1>(g_aoh, nullptr, g_wh + 3 * (size_t)DD_, out, nullptr, nullptr,
                    nullptr, nullptr, 1.0f);
}

// ---------------------------------------------------------------------------
// Flash attention on mma.sync. Q 2-pass in QK^T; P single-pass in PV.
// Softmax in base-2 (log2e folded into q). CTA: 8 warps, Br=128, Bc=64.
// __launch_bounds__(256,2): 2 CTAs/SM.
// ---------------------------------------------------------------------------
#define FS    72                        // smem row stride in halfwords (144 B)
#define QH_E  0
#define QL_E  (128 * FS)                // 9216
#define KV_E  (2 * 128 * FS)            // 18432
#define ARR_E (64 * FS)                 // 4608
#define STG_E (2 * ARR_E)               // 9216 (kh, vh)
#define FA_BYTES ((KV_E + 2 * STG_E) * 2)   // 73728

__global__ void __launch_bounds__(256, 2)
flash_mma()
{
    extern __shared__ __align__(128) char fsmc[];
    const uint32_t sb = smem_u32(fsmc);
    const int tid = threadIdx.x, lane = tid & 31, wid = tid >> 5;
    const int qt = gridDim.x - 1 - blockIdx.x;        // heavy tiles first
    const int bh = blockIdx.y;
    const int b = bh >> 4, h = bh & 15;
    const int g = lane >> 2, t2 = lane & 3;
    const size_t qtok = (size_t)b * T_ + (size_t)qt * 128;

    // --- issue Q loads (hi+lo) ---
#pragma unroll
    for (int i = 0; i < 8; i++) {
        int v = tid + i * 256;                 // 0..2047
        int arr = v >> 10, rem = v & 1023;
        int row = rem >> 3, c = rem & 7;
        const __half* src = arr ? g_ql : g_qh;
        cp16(sb + (uint32_t)((arr ? QL_E : QH_E) + row * FS + c * 8) * 2,
             src + (qtok + row) * D_ + h * 64 + c * 8);
    }

    auto issueKV = [&](int kt, int st) {
        const size_t tok = (size_t)b * T_ + (size_t)kt * 64;
#pragma unroll
        for (int i = 0; i < 4; i++) {
            int v = tid + i * 256;             // 0..1023
            int arr = v >> 9, rem = v & 511;   // 0: kh, 1: vh
            int row = rem >> 3, c = rem & 7;
            cp16(sb + (uint32_t)(KV_E + st * STG_E + arr * ARR_E + row * FS + c * 8) * 2,
                 (arr ? g_vh : g_kh) + (tok + row) * D_ + h * 64 + c * 8);
        }
        CP_COMMIT();
    };

    issueKV(0, 0);
    CP_WAIT(0);
    __syncthreads();

    // --- Q fragments into registers ---
    uint32_t qh[4][4], ql[4][4];
    {
        uint32_t base_r = (uint32_t)((wid * 16 + (lane & 15)) * FS + ((lane >> 4) & 1) * 8);
#pragma unroll
        for (int kg = 0; kg < 4; kg++) {
            ldsm4(qh[kg][0], qh[kg][1], qh[kg][2], qh[kg][3],
                  sb + (QH_E + base_r + kg * 16) * 2);
            ldsm4(ql[kg][0], ql[kg][1], ql[kg][2], ql[kg][3],
                  sb + (QL_E + base_r + kg * 16) * 2);
        }
    }

    float o[8][4];
#pragma unroll
    for (int nt = 0; nt < 8; nt++)
#pragma unroll
        for (int j = 0; j < 4; j++) o[nt][j] = 0.f;
    float m0r = -INFINITY, m1r = -INFINITY, l0 = 0.f, l1 = 0.f;

    const int nkt = 2 * qt + 2;
    const int row0 = qt * 128 + wid * 16 + g;

    for (int kt = 0; kt < nkt; kt++) {
        if (kt + 1 < nkt) issueKV(kt + 1, (kt + 1) & 1);

        const uint32_t kb_h = sb + (uint32_t)(KV_E + (kt & 1) * STG_E) * 2;
        const uint32_t vb_h = kb_h + ARR_E * 2;

        // ---- S = Q K^T (2-pass: q hi + q lo) ----
        float s[8][4];
#pragma unroll
        for (int nt = 0; nt < 8; nt++)
#pragma unroll
            for (int j = 0; j < 4; j++) s[nt][j] = 0.f;

#pragma unroll
        for (int kg = 0; kg < 4; kg++) {
            const uint32_t brow = (uint32_t)(((lane & 7) + ((lane >> 4) & 1) * 8) * FS
                                             + kg * 16 + ((lane >> 3) & 1) * 8) * 2;
#pragma unroll
            for (int pt = 0; pt < 4; pt++) {
                uint32_t k0, k1, k2, k3;
                ldsm4(k0, k1, k2, k3, kb_h + brow + (uint32_t)(pt * 16 * FS) * 2);
                mma16816(s[2 * pt],     qh[kg][0], qh[kg][1], qh[kg][2], qh[kg][3], k0, k1);
                mma16816(s[2 * pt],     ql[kg][0], ql[kg][1], ql[kg][2], ql[kg][3], k0, k1);
                mma16816(s[2 * pt + 1], qh[kg][0], qh[kg][1], qh[kg][2], qh[kg][3], k2, k3);
                mma16816(s[2 * pt + 1], ql[kg][0], ql[kg][1], ql[kg][2], ql[kg][3], k2, k3);
            }
        }

        // ---- causal mask (logits are base-2 scaled) ----
        if (kt * 64 + 63 > qt * 128 + wid * 16) {
#pragma unroll
            for (int nt = 0; nt < 8; nt++) {
#pragma unroll
                for (int j = 0; j < 4; j++) {
                    int col = kt * 64 + nt * 8 + t2 * 2 + (j & 1);
                    int row = row0 + (j >> 1) * 8;
                    if (col > row) s[nt][j] = -1e30f;
                }
            }
        }

        // ---- online softmax (base 2) ----
        float mx0 = -INFINITY, mx1 = -INFINITY;
#pragma unroll
        for (int nt = 0; nt < 8; nt++) {
            mx0 = fmaxf(mx0, fmaxf(s[nt][0], s[nt][1]));
            mx1 = fmaxf(mx1, fmaxf(s[nt][2], s[nt][3]));
        }
        mx0 = fmaxf(mx0, __shfl_xor_sync(0xffffffffu, mx0, 1));
        mx0 = fmaxf(mx0, __shfl_xor_sync(0xffffffffu, mx0, 2));
        mx1 = fmaxf(mx1, __shfl_xor_sync(0xffffffffu, mx1, 1));
        mx1 = fmaxf(mx1, __shfl_xor_sync(0xffffffffu, mx1, 2));

        float mn0 = fmaxf(m0r, mx0), mn1 = fmaxf(m1r, mx1);
        float al0 = ex2f(m0r - mn0), al1 = ex2f(m1r - mn1);
        m0r = mn0; m1r = mn1;

        float su0 = 0.f, su1 = 0.f;
#pragma unroll
        for (int nt = 0; nt < 8; nt++) {
            s[nt][0] = ex2f(s[nt][0] - mn0);
            s[nt][1] = ex2f(s[nt][1] - mn0);
            s[nt][2] = ex2f(s[nt][2] - mn1);
            s[nt][3] = ex2f(s[nt][3] - mn1);
            su0 += s[nt][0] + s[nt][1];
            su1 += s[nt][2] + s[nt][3];
        }
        su0 += __shfl_xor_sync(0xffffffffu, su0, 1);
        su0 += __shfl_xor_sync(0xffffffffu, su0, 2);
        su1 += __shfl_xor_sync(0xffffffffu, su1, 1);
        su1 += __shfl_xor_sync(0xffffffffu, su1, 2);
        l0 = l0 * al0 + su0;
        l1 = l1 * al1 + su1;

#pragma unroll
        for (int nt = 0; nt < 8; nt++) {
            o[nt][0] *= al0; o[nt][1] *= al0;
            o[nt][2] *= al1; o[nt][3] *= al1;
        }

        // ---- O += P V (single-pass; P rounded to fp16) ----
#pragma unroll
        for (int kk = 0; kk < 4; kk++) {
            uint32_t pah[4];
            pah[0] = pack2h(s[2 * kk][0],     s[2 * kk][1]);
            pah[1] = pack2h(s[2 * kk][2],     s[2 * kk][3]);
            pah[2] = pack2h(s[2 * kk + 1][0], s[2 * kk + 1][1]);
            pah[3] = pack2h(s[2 * kk + 1][2], s[2 * kk + 1][3]);

            const uint32_t vrow = (uint32_t)((kk * 16 + (lane & 7) + ((lane >> 3) & 1) * 8) * FS
                                             + ((lane >> 4) & 1) * 8) * 2;
#pragma unroll
            for (int dg = 0; dg < 4; dg++) {
                uint32_t v0, v1, v2, v3;
                ldsm4t(v0, v1, v2, v3, vb_h + vrow + (uint32_t)(dg * 16) * 2);
                mma16816(o[2 * dg],     pah[0], pah[1], pah[2], pah[3], v0, v1);
                mma16816(o[2 * dg + 1], pah[0], pah[1], pah[2], pah[3], v2, v3);
            }
        }

        if (kt + 1 < nkt) CP_WAIT(0);
        __syncthreads();
    }

    // ---- epilogue: normalize, store fp16 hi ----
    const float inv0 = 1.0f / l0, inv1 = 1.0f / l1;
    const size_t tok0 = qtok + (size_t)(wid * 16 + g);
#pragma unroll
    for (int nt = 0; nt < 8; nt++) {
        int col = h * 64 + nt * 8 + t2 * 2;
        *(uint32_t*)(g_aoh + tok0 * D_ + col) =
            pack2h(o[nt][0] * inv0, o[nt][1] * inv0);
        *(uint32_t*)(g_aoh + (tok0 + 8) * D_ + col) =
            pack2h(o[nt][2] * inv1, o[nt][3] * inv1);
    }
}

// ---------------------------------------------------------------------------
// Harness entry
// ---------------------------------------------------------------------------
extern "C" void kernel_launch(void* const* d_in, const int* in_sizes, int n_in,
                              void* d_out, int out_size)
{
    const float* x    = (const float*)d_in[0];
    const float* cosp = (const float*)d_in[1];
    const float* sinp = (const float*)d_in[2];
    const float* wq   = (const float*)d_in[3];
    const float* wk   = (const float*)d_in[4];
    const float* wv   = (const float*)d_in[5];
    const float* wo   = (const float*)d_in[6];
    float* out        = (float*)d_out;

    cudaFuncSetAttribute(gemm_qkv_mma,
                         cudaFuncAttributeMaxDynamicSharedMemorySize, GEMM_SMEM_B);
    cudaFuncSetAttribute(gemm_out_mma,
                         cudaFuncAttributeMaxDynamicSharedMemorySize, GEMM_SMEM_B);
    cudaFuncSetAttribute(flash_mma,
                         cudaFuncAttributeMaxDynamicSharedMemorySize, FA_BYTES);

    // 0) fp32 -> fp16 conversions (x hi/lo, weights hi only)
    {
        int n2x = (M_TOT * D_) / 2;
        split_x_kernel<<<(n2x + 255) / 256, 256>>>(x);
        dim3 wg(DD_ / 2 / 256, 4);
        split_w4_kernel<<<wg, 256>>>(wq, wk, wv, wo);
    }

    // 1) QKV projections with fused RoPE/scale/convert epilogues
    {
        dim3 grid(D_ / 128, M_TOT / 128, 3);
        gemm_qkv_mma<<<grid, 256, GEMM_SMEM_B>>>(cosp, sinp);
    }

    // 2) Causal flash attention -> g_aoh
    {
        dim3 grid(T_ / 128, B_ * H_);
        flash_mma<<<grid, 256, FA_BYTES>>>();
    }

    // 3) Output projection (single-pass A)
    {
        dim3 grid(D_ / 128, M_TOT / 128, 1);
        gemm_out_mma<<<grid, 256, GEMM_SMEM_B>>>(out);
    }
}

// round 12
// speedup vs baseline: 2.5734x; 1.1433x over previous
#include <cuda_runtime.h>
#include <cuda_fp16.h>
#include <math.h>
#include <stdint.h>

// Problem dims (fixed by the reference)
#define B_   4
#define T_   2048
#define D_   1024
#define H_   16
#define HD_  64
#define M_TOT (B_*T_)   // 8192
#define DD_  (D_*D_)

// ---------------------------------------------------------------------------
// Device-global scratch (allocation-free rule). fp16; hi/lo only where needed.
// ---------------------------------------------------------------------------
__device__ __align__(128) __half g_xh [M_TOT * D_];
__device__ __align__(128) __half g_qh [M_TOT * D_];
__device__ __align__(128) __half g_ql [M_TOT * D_];
__device__ __align__(128) __half g_kh [M_TOT * D_];
__device__ __align__(128) __half g_vh [M_TOT * D_];
__device__ __align__(128) __half g_aoh[M_TOT * D_];
__device__ __align__(128) __half g_wh [4 * DD_];   // q,k,v,o (hi only)

// ---------------------------------------------------------------------------
// PTX helpers (target-independent, sm_80-era)
// ---------------------------------------------------------------------------
__device__ __forceinline__ uint32_t smem_u32(const void* p) {
    uint32_t a;
    asm("{ .reg .u64 t; cvta.to.shared.u64 t, %1; cvt.u32.u64 %0, t; }"
        : "=r"(a) : "l"(p));
    return a;
}

__device__ __forceinline__ void cp16(uint32_t dst, const void* src) {
    asm volatile("cp.async.cg.shared.global [%0], [%1], 16;"
                 :: "r"(dst), "l"(src));
}
#define CP_COMMIT() asm volatile("cp.async.commit_group;" ::: "memory")
#define CP_WAIT(n)  asm volatile("cp.async.wait_group %0;" :: "n"(n) : "memory")

__device__ __forceinline__ void ldsm4(uint32_t& r0, uint32_t& r1,
                                      uint32_t& r2, uint32_t& r3, uint32_t a) {
    asm volatile("ldmatrix.sync.aligned.m8n8.x4.shared.b16 {%0,%1,%2,%3}, [%4];"
                 : "=r"(r0), "=r"(r1), "=r"(r2), "=r"(r3) : "r"(a));
}
__device__ __forceinline__ void ldsm4t(uint32_t& r0, uint32_t& r1,
                                       uint32_t& r2, uint32_t& r3, uint32_t a) {
    asm volatile("ldmatrix.sync.aligned.m8n8.x4.trans.shared.b16 {%0,%1,%2,%3}, [%4];"
                 : "=r"(r0), "=r"(r1), "=r"(r2), "=r"(r3) : "r"(a));
}

__device__ __forceinline__ void mma16816(float* c,
                                         uint32_t a0, uint32_t a1,
                                         uint32_t a2, uint32_t a3,
                                         uint32_t b0, uint32_t b1) {
    asm volatile("mma.sync.aligned.m16n8k16.row.col.f32.f16.f16.f32 "
                 "{%0,%1,%2,%3}, {%4,%5,%6,%7}, {%8,%9}, {%0,%1,%2,%3};"
                 : "+f"(c[0]), "+f"(c[1]), "+f"(c[2]), "+f"(c[3])
                 : "r"(a0), "r"(a1), "r"(a2), "r"(a3), "r"(b0), "r"(b1));
}

__device__ __forceinline__ float ex2f(float x) {
    float y;
    asm("ex2.approx.ftz.f32 %0, %1;" : "=f"(y) : "f"(x));
    return y;
}

// fp32 pair -> packed fp16 hi pair + lo pair
__device__ __forceinline__ void split_pack2(float x, float y,
                                            uint32_t& hp, uint32_t& lp) {
    __half hx = __float2half(x);
    __half hy = __float2half(y);
    __half lx = __float2half(x - __half2float(hx));
    __half ly = __float2half(y - __half2float(hy));
    hp = (uint32_t)__half_as_ushort(hx) | ((uint32_t)__half_as_ushort(hy) << 16);
    lp = (uint32_t)__half_as_ushort(lx) | ((uint32_t)__half_as_ushort(ly) << 16);
}
__device__ __forceinline__ uint32_t pack2h(float x, float y) {
    return (uint32_t)__half_as_ushort(__float2half(x)) |
           ((uint32_t)__half_as_ushort(__float2half(y)) << 16);
}

// ---------------------------------------------------------------------------
// Input conversion kernels (single fp16 everywhere now)
// ---------------------------------------------------------------------------
__global__ void __launch_bounds__(256)
split_x_kernel(const float* __restrict__ src)
{
    int i = blockIdx.x * 256 + threadIdx.x;
    if (i >= M_TOT * D_ / 2) return;
    float2 a = ((const float2*)src)[i];
    ((uint32_t*)g_xh)[i] = pack2h(a.x, a.y);
}

__global__ void __launch_bounds__(256)
split_w4_kernel(const float* __restrict__ wq, const float* __restrict__ wk,
                const float* __restrict__ wv, const float* __restrict__ wo)
{
    int i = blockIdx.x * 256 + threadIdx.x;           // < DD_/2 exactly
    const float* srcs[4] = { wq, wk, wv, wo };
    float2 a = ((const float2*)srcs[blockIdx.y])[i];
    ((uint32_t*)(g_wh + (size_t)blockIdx.y * DD_))[i] = pack2h(a.x, a.y);
}

// ---------------------------------------------------------------------------
// fp16 GEMM: C[M,N] = A[M,K] * W[N,K]^T ; NPASS=2 adds the A-lo pass.
// CTA tile 128x128, BK=32, 8 warps (4m x 2n), 2-stage cp.async pipeline.
// MODE 0: fp32 out. 1: RoPE+scale hi/lo. 2: hi only. 3: RoPE hi only.
// ---------------------------------------------------------------------------
#define ROWB 40                         // smem row stride in halfwords (80 B)
#define S_AH 0
#define S_AL (128 * ROWB)               // 5120 h
#define S_BH (256 * ROWB)               // 10240 h
#define STAGE_E (384 * ROWB)            // 15360 h
#define STAGE_B (STAGE_E * 2)           // 30720 B
#define GEMM_SMEM_B (2 * STAGE_B)       // 61440 B

template <int MODE, int NPASS>
__device__ void gemm_core(const __half* __restrict__ Ah,
                          const __half* __restrict__ Al,
                          const __half* __restrict__ Bh,
                          float* __restrict__ Cf,
                          __half* __restrict__ Ch,
                          __half* __restrict__ Cl,
                          const float* __restrict__ cosp,
                          const float* __restrict__ sinp,
                          float qscale)
{
    extern __shared__ __align__(128) char smem[];
    const uint32_t sb = smem_u32(smem);
    const int tid  = threadIdx.x;
    const int lane = tid & 31;
    const int wid  = tid >> 5;
    const int warp_m = wid & 3;         // 32 rows
    const int warp_n = wid >> 2;        // 64 cols
    const int m0 = blockIdx.y * 128;
    const int n0 = blockIdx.x * 128;

    const int a_row = lane & 15;
    const int a_col = (lane >> 4) << 3;
    const int b_row = (lane & 7) + ((lane >> 4) << 3);
    const int b_col = ((lane >> 3) & 1) << 3;

    float acc[2][8][4];
#pragma unroll
    for (int mt = 0; mt < 2; mt++)
#pragma unroll
        for (int nt = 0; nt < 8; nt++)
#pragma unroll
            for (int r = 0; r < 4; r++) acc[mt][nt][r] = 0.f;

    auto issue = [&](int st, int k0) {
        const uint32_t dstb = sb + st * STAGE_B;
#pragma unroll
        for (int i = 0; i < 6; i++) {
            if (NPASS == 1 && i >= 2 && i < 4) continue;
            int v = (tid + (i & 1) * 256);              // 0..511
            int r = v >> 2, c = v & 3;
            if (i < 2)
                cp16(dstb + (uint32_t)(S_AH + r * ROWB + c * 8) * 2,
                     Ah + (size_t)(m0 + r) * D_ + k0 + c * 8);
            else if (i < 4)
                cp16(dstb + (uint32_t)(S_AL + r * ROWB + c * 8) * 2,
                     Al + (size_t)(m0 + r) * D_ + k0 + c * 8);
            else
                cp16(dstb + (uint32_t)(S_BH + r * ROWB + c * 8) * 2,
                     Bh + (size_t)(n0 + r) * D_ + k0 + c * 8);
        }
        CP_COMMIT();
    };

    const int NIT = D_ / 32;                // 32
    issue(0, 0);
    for (int ic = 0; ic < NIT; ic++) {
        if (ic + 1 < NIT) {
            issue((ic + 1) & 1, (ic + 1) * 32);
            CP_WAIT(1);
        } else {
            CP_WAIT(0);
        }
        __syncthreads();

        const uint32_t sa = sb + (ic & 1) * STAGE_B;
#pragma unroll
        for (int ks = 0; ks < 2; ks++) {
            uint32_t ah[2][4], al_[2][4];
#pragma unroll
            for (int mt = 0; mt < 2; mt++) {
                uint32_t ra = sa + (uint32_t)((warp_m * 32 + mt * 16 + a_row) * ROWB
                                              + ks * 16 + a_col) * 2;
                ldsm4(ah[mt][0],  ah[mt][1],  ah[mt][2],  ah[mt][3],  ra + S_AH * 2);
                if (NPASS == 2)
                    ldsm4(al_[mt][0], al_[mt][1], al_[mt][2], al_[mt][3], ra + S_AL * 2);
            }
#pragma unroll
            for (int pt = 0; pt < 4; pt++) {
                uint32_t b0, b1, b2, b3;
                uint32_t rb = sa + (uint32_t)(S_BH + (warp_n * 64 + pt * 16 + b_row) * ROWB
                                              + ks * 16 + b_col) * 2;
                ldsm4(b0, b1, b2, b3, rb);
#pragma unroll
                for (int mt = 0; mt < 2; mt++) {
                    mma16816(acc[mt][2 * pt],     ah[mt][0],  ah[mt][1],  ah[mt][2],  ah[mt][3],  b0, b1);
                    mma16816(acc[mt][2 * pt + 1], ah[mt][0],  ah[mt][1],  ah[mt][2],  ah[mt][3],  b2, b3);
                    if (NPASS == 2) {
                        mma16816(acc[mt][2 * pt],     al_[mt][0], al_[mt][1], al_[mt][2], al_[mt][3], b0, b1);
                        mma16816(acc[mt][2 * pt + 1], al_[mt][0], al_[mt][1], al_[mt][2], al_[mt][3], b2, b3);
                    }
                }
            }
        }
        __syncthreads();
    }

    const int g = lane >> 2, t2 = lane & 3;
    if (MODE == 0) {
#pragma unroll
        for (int mt = 0; mt < 2; mt++) {
            int r0 = m0 + warp_m * 32 + mt * 16 + g;
#pragma unroll
            for (int nt = 0; nt < 8; nt++) {
                int col = n0 + warp_n * 64 + nt * 8 + t2 * 2;
                *(float2*)(Cf + (size_t)r0 * D_ + col) =
                    make_float2(acc[mt][nt][0], acc[mt][nt][1]);
                *(float2*)(Cf + (size_t)(r0 + 8) * D_ + col) =
                    make_float2(acc[mt][nt][2], acc[mt][nt][3]);
            }
        }
    } else if (MODE == 1 || MODE == 3) {
        // RoPE: head-local pairs (d, d+32) live in nt and nt+4 (warp_n*64 = head half)
#pragma unroll
        for (int mt = 0; mt < 2; mt++) {
#pragma unroll
            for (int ri = 0; ri < 2; ri++) {
                int row = m0 + warp_m * 32 + mt * 16 + g + ri * 8;
                int t = row & (T_ - 1);
#pragma unroll
                for (int nt = 0; nt < 4; nt++) {
                    int d = nt * 8 + t2 * 2;                  // < 32
                    float2 cc = *(const float2*)(cosp + t * HD_ + d);
                    float2 ss = *(const float2*)(sinp + t * HD_ + d);
                    float v0 = acc[mt][nt][ri * 2],     v1 = acc[mt][nt][ri * 2 + 1];
                    float w0 = acc[mt][nt + 4][ri * 2], w1 = acc[mt][nt + 4][ri * 2 + 1];
                    float q0 = (v0 * cc.x - w0 * ss.x) * qscale;
                    float q1 = (v1 * cc.y - w1 * ss.y) * qscale;
                    float p0 = (w0 * cc.x + v0 * ss.x) * qscale;
                    float p1 = (w1 * cc.y + v1 * ss.y) * qscale;
                    int col = n0 + warp_n * 64 + d;
                    if (MODE == 1) {
                        uint32_t hp, lp;
                        split_pack2(q0, q1, hp, lp);
                        *(uint32_t*)(Ch + (size_t)row * D_ + col) = hp;
                        *(uint32_t*)(Cl + (size_t)row * D_ + col) = lp;
                        split_pack2(p0, p1, hp, lp);
                        *(uint32_t*)(Ch + (size_t)row * D_ + col + 32) = hp;
                        *(uint32_t*)(Cl + (size_t)row * D_ + col + 32) = lp;
                    } else {
                        *(uint32_t*)(Ch + (size_t)row * D_ + col)      = pack2h(q0, q1);
                        *(uint32_t*)(Ch + (size_t)row * D_ + col + 32) = pack2h(p0, p1);
                    }
                }
            }
        }
    } else {   // MODE 2: hi only
#pragma unroll
        for (int mt = 0; mt < 2; mt++) {
#pragma unroll
            for (int ri = 0; ri < 2; ri++) {
                int row = m0 + warp_m * 32 + mt * 16 + g + ri * 8;
#pragma unroll
                for (int nt = 0; nt < 8; nt++) {
                    int col = n0 + warp_n * 64 + nt * 8 + t2 * 2;
                    *(uint32_t*)(Ch + (size_t)row * D_ + col) =
                        pack2h(acc[mt][nt][ri * 2], acc[mt][nt][ri * 2 + 1]);
                }
            }
        }
    }
}

// log2(e) folded into q so flash softmax can use raw ex2
#define QSCALE_LOG2E (0.125f * 1.44269504088896f)

__global__ void __launch_bounds__(256, 2)
gemm_qkv_mma(const float* __restrict__ cosp, const float* __restrict__ sinp)
{
    const int z = blockIdx.z;
    if (z == 0)
        gemm_core<1, 1>(g_xh, nullptr, g_wh, nullptr, g_qh, g_ql, cosp, sinp, QSCALE_LOG2E);
    else if (z == 1)
        gemm_core<3, 1>(g_xh, nullptr, g_wh + DD_, nullptr, g_kh, nullptr, cosp, sinp, 1.0f);
    else
        gemm_core<2, 1>(g_xh, nullptr, g_wh + 2 * (size_t)DD_, nullptr, g_vh, nullptr,
                        nullptr, nullptr, 1.0f);
}

__global__ void __launch_bounds__(256, 2)
gemm_out_mma(float* __restrict__ out)
{
    gemm_core<0, 1>(g_aoh, nullptr, g_wh + 3 * (size_t)DD_, out, nullptr, nullptr,
                    nullptr, nullptr, 1.0f);
}

// ---------------------------------------------------------------------------
// Flash attention on mma.sync. Q 2-pass in QK^T; P single-pass in PV.
// Softmax in base-2 (log2e folded into q). CTA: 8 warps, Br=128, Bc=64.
// __launch_bounds__(256,2): 2 CTAs/SM.
// ---------------------------------------------------------------------------
#define FS    72                        // smem row stride in halfwords (144 B)
#define QH_E  0
#define QL_E  (128 * FS)                // 9216
#define KV_E  (2 * 128 * FS)            // 18432
#define ARR_E (64 * FS)                 // 4608
#define STG_E (2 * ARR_E)               // 9216 (kh, vh)
#define FA_BYTES ((KV_E + 2 * STG_E) * 2)   // 73728

__global__ void __launch_bounds__(256, 2)
flash_mma()
{
    extern __shared__ __align__(128) char fsmc[];
    const uint32_t sb = smem_u32(fsmc);
    const int tid = threadIdx.x, lane = tid & 31, wid = tid >> 5;
    const int qt = gridDim.x - 1 - blockIdx.x;        // heavy tiles first
    const int bh = blockIdx.y;
    const int b = bh >> 4, h = bh & 15;
    const int g = lane >> 2, t2 = lane & 3;
    const size_t qtok = (size_t)b * T_ + (size_t)qt * 128;

    // --- issue Q loads (hi+lo) ---
#pragma unroll
    for (int i = 0; i < 8; i++) {
        int v = tid + i * 256;                 // 0..2047
        int arr = v >> 10, rem = v & 1023;
        int row = rem >> 3, c = rem & 7;
        const __half* src = arr ? g_ql : g_qh;
        cp16(sb + (uint32_t)((arr ? QL_E : QH_E) + row * FS + c * 8) * 2,
             src + (qtok + row) * D_ + h * 64 + c * 8);
    }

    auto issueKV = [&](int kt, int st) {
        const size_t tok = (size_t)b * T_ + (size_t)kt * 64;
#pragma unroll
        for (int i = 0; i < 4; i++) {
            int v = tid + i * 256;             // 0..1023
            int arr = v >> 9, rem = v & 511;   // 0: kh, 1: vh
            int row = rem >> 3, c = rem & 7;
            cp16(sb + (uint32_t)(KV_E + st * STG_E + arr * ARR_E + row * FS + c * 8) * 2,
                 (arr ? g_vh : g_kh) + (tok + row) * D_ + h * 64 + c * 8);
        }
        CP_COMMIT();
    };

    issueKV(0, 0);
    CP_WAIT(0);
    __syncthreads();

    // --- Q fragments into registers ---
    uint32_t qh[4][4], ql[4][4];
    {
        uint32_t base_r = (uint32_t)((wid * 16 + (lane & 15)) * FS + ((lane >> 4) & 1) * 8);
#pragma unroll
        for (int kg = 0; kg < 4; kg++) {
            ldsm4(qh[kg][0], qh[kg][1], qh[kg][2], qh[kg][3],
                  sb + (QH_E + base_r + kg * 16) * 2);
            ldsm4(ql[kg][0], ql[kg][1], ql[kg][2], ql[kg][3],
                  sb + (QL_E + base_r + kg * 16) * 2);
        }
    }

    float o[8][4];
#pragma unroll
    for (int nt = 0; nt < 8; nt++)
#pragma unroll
        for (int j = 0; j < 4; j++) o[nt][j] = 0.f;
    float m0r = -INFINITY, m1r = -INFINITY, l0 = 0.f, l1 = 0.f;

    const int nkt = 2 * qt + 2;
    const int row0 = qt * 128 + wid * 16 + g;

    for (int kt = 0; kt < nkt; kt++) {
        if (kt + 1 < nkt) issueKV(kt + 1, (kt + 1) & 1);

        const uint32_t kb_h = sb + (uint32_t)(KV_E + (kt & 1) * STG_E) * 2;
        const uint32_t vb_h = kb_h + ARR_E * 2;

        // ---- S = Q K^T (2-pass: q hi + q lo) ----
        float s[8][4];
#pragma unroll
        for (int nt = 0; nt < 8; nt++)
#pragma unroll
            for (int j = 0; j < 4; j++) s[nt][j] = 0.f;

#pragma unroll
        for (int kg = 0; kg < 4; kg++) {
            const uint32_t brow = (uint32_t)(((lane & 7) + ((lane >> 4) & 1) * 8) * FS
                                             + kg * 16 + ((lane >> 3) & 1) * 8) * 2;
#pragma unroll
            for (int pt = 0; pt < 4; pt++) {
                uint32_t k0, k1, k2, k3;
                ldsm4(k0, k1, k2, k3, kb_h + brow + (uint32_t)(pt * 16 * FS) * 2);
                mma16816(s[2 * pt],     qh[kg][0], qh[kg][1], qh[kg][2], qh[kg][3], k0, k1);
                mma16816(s[2 * pt],     ql[kg][0], ql[kg][1], ql[kg][2], ql[kg][3], k0, k1);
                mma16816(s[2 * pt + 1], qh[kg][0], qh[kg][1], qh[kg][2], qh[kg][3], k2, k3);
                mma16816(s[2 * pt + 1], ql[kg][0], ql[kg][1], ql[kg][2], ql[kg][3], k2, k3);
            }
        }

        // ---- causal mask (logits are base-2 scaled) ----
        if (kt * 64 + 63 > qt * 128 + wid * 16) {
#pragma unroll
            for (int nt = 0; nt < 8; nt++) {
#pragma unroll
                for (int j = 0; j < 4; j++) {
                    int col = kt * 64 + nt * 8 + t2 * 2 + (j & 1);
                    int row = row0 + (j >> 1) * 8;
                    if (col > row) s[nt][j] = -1e30f;
                }
            }
        }

        // ---- online softmax (base 2) ----
        float mx0 = -INFINITY, mx1 = -INFINITY;
#pragma unroll
        for (int nt = 0; nt < 8; nt++) {
            mx0 = fmaxf(mx0, fmaxf(s[nt][0], s[nt][1]));
            mx1 = fmaxf(mx1, fmaxf(s[nt][2], s[nt][3]));
        }
        mx0 = fmaxf(mx0, __shfl_xor_sync(0xffffffffu, mx0, 1));
        mx0 = fmaxf(mx0, __shfl_xor_sync(0xffffffffu, mx0, 2));
        mx1 = fmaxf(mx1, __shfl_xor_sync(0xffffffffu, mx1, 1));
        mx1 = fmaxf(mx1, __shfl_xor_sync(0xffffffffu, mx1, 2));

        float mn0 = fmaxf(m0r, mx0), mn1 = fmaxf(m1r, mx1);
        float al0 = ex2f(m0r - mn0), al1 = ex2f(m1r - mn1);
        m0r = mn0; m1r = mn1;

        float su0 = 0.f, su1 = 0.f;
#pragma unroll
        for (int nt = 0; nt < 8; nt++) {
            s[nt][0] = ex2f(s[nt][0] - mn0);
            s[nt][1] = ex2f(s[nt][1] - mn0);
            s[nt][2] = ex2f(s[nt][2] - mn1);
            s[nt][3] = ex2f(s[nt][3] - mn1);
            su0 += s[nt][0] + s[nt][1];
            su1 += s[nt][2] + s[nt][3];
        }
        su0 += __shfl_xor_sync(0xffffffffu, su0, 1);
        su0 += __shfl_xor_sync(0xffffffffu, su0, 2);
        su1 += __shfl_xor_sync(0xffffffffu, su1, 1);
        su1 += __shfl_xor_sync(0xffffffffu, su1, 2);
        l0 = l0 * al0 + su0;
        l1 = l1 * al1 + su1;

#pragma unroll
        for (int nt = 0; nt < 8; nt++) {
            o[nt][0] *= al0; o[nt][1] *= al0;
            o[nt][2] *= al1; o[nt][3] *= al1;
        }

        // ---- O += P V (single-pass; P rounded to fp16) ----
#pragma unroll
        for (int kk = 0; kk < 4; kk++) {
            uint32_t pah[4];
            pah[0] = pack2h(s[2 * kk][0],     s[2 * kk][1]);
            pah[1] = pack2h(s[2 * kk][2],     s[2 * kk][3]);
            pah[2] = pack2h(s[2 * kk + 1][0], s[2 * kk + 1][1]);
            pah[3] = pack2h(s[2 * kk + 1][2], s[2 * kk + 1][3]);

            const uint32_t vrow = (uint32_t)((kk * 16 + (lane & 7) + ((lane >> 3) & 1) * 8) * FS
                                             + ((lane >> 4) & 1) * 8) * 2;
#pragma unroll
            for (int dg = 0; dg < 4; dg++) {
                uint32_t v0, v1, v2, v3;
                ldsm4t(v0, v1, v2, v3, vb_h + vrow + (uint32_t)(dg * 16) * 2);
                mma16816(o[2 * dg],     pah[0], pah[1], pah[2], pah[3], v0, v1);
                mma16816(o[2 * dg + 1], pah[0], pah[1], pah[2], pah[3], v2, v3);
            }
        }

        if (kt + 1 < nkt) CP_WAIT(0);
        __syncthreads();
    }

    // ---- epilogue: normalize, store fp16 hi ----
    const float inv0 = 1.0f / l0, inv1 = 1.0f / l1;
    const size_t tok0 = qtok + (size_t)(wid * 16 + g);
#pragma unroll
    for (int nt = 0; nt < 8; nt++) {
        int col = h * 64 + nt * 8 + t2 * 2;
        *(uint32_t*)(g_aoh + tok0 * D_ + col) =
            pack2h(o[nt][0] * inv0, o[nt][1] * inv0);
        *(uint32_t*)(g_aoh + (tok0 + 8) * D_ + col) =
            pack2h(o[nt][2] * inv1, o[nt][3] * inv1);
    }
}

// ---------------------------------------------------------------------------
// Harness entry
// ---------------------------------------------------------------------------
extern "C" void kernel_launch(void* const* d_in, const int* in_sizes, int n_in,
                              void* d_out, int out_size)
{
    const float* x    = (const float*)d_in[0];
    const float* cosp = (const float*)d_in[1];
    const float* sinp = (const float*)d_in[2];
    const float* wq   = (const float*)d_in[3];
    const float* wk   = (const float*)d_in[4];
    const float* wv   = (const float*)d_in[5];
    const float* wo   = (const float*)d_in[6];
    float* out        = (float*)d_out;

    cudaFuncSetAttribute(gemm_qkv_mma,
                         cudaFuncAttributeMaxDynamicSharedMemorySize, GEMM_SMEM_B);
    cudaFuncSetAttribute(gemm_out_mma,
                         cudaFuncAttributeMaxDynamicSharedMemorySize, GEMM_SMEM_B);
    cudaFuncSetAttribute(flash_mma,
                         cudaFuncAttributeMaxDynamicSharedMemorySize, FA_BYTES);

    // 0) fp32 -> fp16 conversions (all single fp16 now)
    {
        int n2x = (M_TOT * D_) / 2;
        split_x_kernel<<<(n2x + 255) / 256, 256>>>(x);
        dim3 wg(DD_ / 2 / 256, 4);
        split_w4_kernel<<<wg, 256>>>(wq, wk, wv, wo);
    }

    // 1) QKV projections with fused RoPE/scale/convert epilogues (single-pass)
    {
        dim3 grid(D_ / 128, M_TOT / 128, 3);
        gemm_qkv_mma<<<grid, 256, GEMM_SMEM_B>>>(cosp, sinp);
    }

    // 2) Causal flash attention -> g_aoh
    {
        dim3 grid(T_ / 128, B_ * H_);
        flash_mma<<<grid, 256, FA_BYTES>>>();
    }

    // 3) Output projection (single-pass A)
    {
        dim3 grid(D_ / 128, M_TOT / 128, 1);
        gemm_out_mma<<<grid, 256, GEMM_SMEM_B>>>(out);
    }
}

// round 14
// speedup vs baseline: 2.7820x; 1.0811x over previous
#include <cuda_runtime.h>
#include <cuda_fp16.h>
#include <math.h>
#include <stdint.h>

// Problem dims (fixed by the reference)
#define B_   4
#define T_   2048
#define D_   1024
#define H_   16
#define HD_  64
#define M_TOT (B_*T_)   // 8192
#define DD_  (D_*D_)

// ---------------------------------------------------------------------------
// Device-global scratch (allocation-free rule). Single fp16 everywhere now.
// ---------------------------------------------------------------------------
__device__ __align__(128) __half g_xh [M_TOT * D_];
__device__ __align__(128) __half g_qh [M_TOT * D_];
__device__ __align__(128) __half g_kh [M_TOT * D_];
__device__ __align__(128) __half g_vh [M_TOT * D_];
__device__ __align__(128) __half g_aoh[M_TOT * D_];
__device__ __align__(128) __half g_wh [4 * DD_];   // q,k,v,o

// ---------------------------------------------------------------------------
// PTX helpers (target-independent, sm_80-era)
// ---------------------------------------------------------------------------
__device__ __forceinline__ uint32_t smem_u32(const void* p) {
    uint32_t a;
    asm("{ .reg .u64 t; cvta.to.shared.u64 t, %1; cvt.u32.u64 %0, t; }"
        : "=r"(a) : "l"(p));
    return a;
}

__device__ __forceinline__ void cp16(uint32_t dst, const void* src) {
    asm volatile("cp.async.cg.shared.global [%0], [%1], 16;"
                 :: "r"(dst), "l"(src));
}
#define CP_COMMIT() asm volatile("cp.async.commit_group;" ::: "memory")
#define CP_WAIT(n)  asm volatile("cp.async.wait_group %0;" :: "n"(n) : "memory")

__device__ __forceinline__ void ldsm4(uint32_t& r0, uint32_t& r1,
                                      uint32_t& r2, uint32_t& r3, uint32_t a) {
    asm volatile("ldmatrix.sync.aligned.m8n8.x4.shared.b16 {%0,%1,%2,%3}, [%4];"
                 : "=r"(r0), "=r"(r1), "=r"(r2), "=r"(r3) : "r"(a));
}
__device__ __forceinline__ void ldsm4t(uint32_t& r0, uint32_t& r1,
                                       uint32_t& r2, uint32_t& r3, uint32_t a) {
    asm volatile("ldmatrix.sync.aligned.m8n8.x4.trans.shared.b16 {%0,%1,%2,%3}, [%4];"
                 : "=r"(r0), "=r"(r1), "=r"(r2), "=r"(r3) : "r"(a));
}

__device__ __forceinline__ void mma16816(float* c,
                                         uint32_t a0, uint32_t a1,
                                         uint32_t a2, uint32_t a3,
                                         uint32_t b0, uint32_t b1) {
    asm volatile("mma.sync.aligned.m16n8k16.row.col.f32.f16.f16.f32 "
                 "{%0,%1,%2,%3}, {%4,%5,%6,%7}, {%8,%9}, {%0,%1,%2,%3};"
                 : "+f"(c[0]), "+f"(c[1]), "+f"(c[2]), "+f"(c[3])
                 : "r"(a0), "r"(a1), "r"(a2), "r"(a3), "r"(b0), "r"(b1));
}

__device__ __forceinline__ float ex2f(float x) {
    float y;
    asm("ex2.approx.ftz.f32 %0, %1;" : "=f"(y) : "f"(x));
    return y;
}

__device__ __forceinline__ uint32_t pack2h(float x, float y) {
    return (uint32_t)__half_as_ushort(__float2half(x)) |
           ((uint32_t)__half_as_ushort(__float2half(y)) << 16);
}

// ---------------------------------------------------------------------------
// Input conversion kernels
// ---------------------------------------------------------------------------
__global__ void __launch_bounds__(256)
split_x_kernel(const float* __restrict__ src)
{
    int i = blockIdx.x * 256 + threadIdx.x;
    if (i >= M_TOT * D_ / 2) return;
    float2 a = ((const float2*)src)[i];
    ((uint32_t*)g_xh)[i] = pack2h(a.x, a.y);
}

__global__ void __launch_bounds__(256)
split_w4_kernel(const float* __restrict__ wq, const float* __restrict__ wk,
                const float* __restrict__ wv, const float* __restrict__ wo)
{
    int i = blockIdx.x * 256 + threadIdx.x;           // < DD_/2 exactly
    const float* srcs[4] = { wq, wk, wv, wo };
    float2 a = ((const float2*)srcs[blockIdx.y])[i];
    ((uint32_t*)(g_wh + (size_t)blockIdx.y * DD_))[i] = pack2h(a.x, a.y);
}

// ---------------------------------------------------------------------------
// fp16 single-pass GEMM: C[M,N] = A[M,K] * W[N,K]^T
// CTA tile 128x128, BK=32, 8 warps (4m x 2n), 2-stage cp.async pipeline.
// MODE 0: fp32 out. 2: fp16 out. 3: RoPE+scale fp16 out.
// ---------------------------------------------------------------------------
#define ROWB 40                         // smem row stride in halfwords (80 B)
#define S_AH 0
#define S_BH (128 * ROWB)               // 5120 h
#define STAGE_E (256 * ROWB)            // 10240 h
#define STAGE_B (STAGE_E * 2)           // 20480 B
#define GEMM_SMEM_B (2 * STAGE_B)       // 40960 B

template <int MODE>
__device__ void gemm_core(const __half* __restrict__ Ah,
                          const __half* __restrict__ Bh,
                          float* __restrict__ Cf,
                          __half* __restrict__ Ch,
                          const float* __restrict__ cosp,
                          const float* __restrict__ sinp,
                          float qscale)
{
    extern __shared__ __align__(128) char smem[];
    const uint32_t sb = smem_u32(smem);
    const int tid  = threadIdx.x;
    const int lane = tid & 31;
    const int wid  = tid >> 5;
    const int warp_m = wid & 3;         // 32 rows
    const int warp_n = wid >> 2;        // 64 cols
    const int m0 = blockIdx.y * 128;
    const int n0 = blockIdx.x * 128;

    const int a_row = lane & 15;
    const int a_col = (lane >> 4) << 3;
    const int b_row = (lane & 7) + ((lane >> 4) << 3);
    const int b_col = ((lane >> 3) & 1) << 3;

    float acc[2][8][4];
#pragma unroll
    for (int mt = 0; mt < 2; mt++)
#pragma unroll
        for (int nt = 0; nt < 8; nt++)
#pragma unroll
            for (int r = 0; r < 4; r++) acc[mt][nt][r] = 0.f;

    auto issue = [&](int st, int k0) {
        const uint32_t dstb = sb + st * STAGE_B;
#pragma unroll
        for (int i = 0; i < 4; i++) {
            int v = (tid + (i & 1) * 256);              // 0..511
            int r = v >> 2, c = v & 3;
            if (i < 2)
                cp16(dstb + (uint32_t)(S_AH + r * ROWB + c * 8) * 2,
                     Ah + (size_t)(m0 + r) * D_ + k0 + c * 8);
            else
                cp16(dstb + (uint32_t)(S_BH + r * ROWB + c * 8) * 2,
                     Bh + (size_t)(n0 + r) * D_ + k0 + c * 8);
        }
        CP_COMMIT();
    };

    const int NIT = D_ / 32;                // 32
    issue(0, 0);
    for (int ic = 0; ic < NIT; ic++) {
        if (ic + 1 < NIT) {
            issue((ic + 1) & 1, (ic + 1) * 32);
            CP_WAIT(1);
        } else {
            CP_WAIT(0);
        }
        __syncthreads();

        const uint32_t sa = sb + (ic & 1) * STAGE_B;
#pragma unroll
        for (int ks = 0; ks < 2; ks++) {
            uint32_t ah[2][4];
#pragma unroll
            for (int mt = 0; mt < 2; mt++) {
                uint32_t ra = sa + (uint32_t)((warp_m * 32 + mt * 16 + a_row) * ROWB
                                              + ks * 16 + a_col) * 2;
                ldsm4(ah[mt][0], ah[mt][1], ah[mt][2], ah[mt][3], ra + S_AH * 2);
            }
#pragma unroll
            for (int pt = 0; pt < 4; pt++) {
                uint32_t b0, b1, b2, b3;
                uint32_t rb = sa + (uint32_t)(S_BH + (warp_n * 64 + pt * 16 + b_row) * ROWB
                                              + ks * 16 + b_col) * 2;
                ldsm4(b0, b1, b2, b3, rb);
#pragma unroll
                for (int mt = 0; mt < 2; mt++) {
                    mma16816(acc[mt][2 * pt],     ah[mt][0], ah[mt][1], ah[mt][2], ah[mt][3], b0, b1);
                    mma16816(acc[mt][2 * pt + 1], ah[mt][0], ah[mt][1], ah[mt][2], ah[mt][3], b2, b3);
                }
            }
        }
        __syncthreads();
    }

    const int g = lane >> 2, t2 = lane & 3;
    if (MODE == 0) {
#pragma unroll
        for (int mt = 0; mt < 2; mt++) {
            int r0 = m0 + warp_m * 32 + mt * 16 + g;
#pragma unroll
            for (int nt = 0; nt < 8; nt++) {
                int col = n0 + warp_n * 64 + nt * 8 + t2 * 2;
                *(float2*)(Cf + (size_t)r0 * D_ + col) =
                    make_float2(acc[mt][nt][0], acc[mt][nt][1]);
                *(float2*)(Cf + (size_t)(r0 + 8) * D_ + col) =
                    make_float2(acc[mt][nt][2], acc[mt][nt][3]);
            }
        }
    } else if (MODE == 3) {
        // RoPE: head-local pairs (d, d+32) live in nt and nt+4 (warp_n*64 = head half)
#pragma unroll
        for (int mt = 0; mt < 2; mt++) {
#pragma unroll
            for (int ri = 0; ri < 2; ri++) {
                int row = m0 + warp_m * 32 + mt * 16 + g + ri * 8;
                int t = row & (T_ - 1);
#pragma unroll
                for (int nt = 0; nt < 4; nt++) {
                    int d = nt * 8 + t2 * 2;                  // < 32
                    float2 cc = *(const float2*)(cosp + t * HD_ + d);
                    float2 ss = *(const float2*)(sinp + t * HD_ + d);
                    float v0 = acc[mt][nt][ri * 2],     v1 = acc[mt][nt][ri * 2 + 1];
                    float w0 = acc[mt][nt + 4][ri * 2], w1 = acc[mt][nt + 4][ri * 2 + 1];
                    float q0 = (v0 * cc.x - w0 * ss.x) * qscale;
                    float q1 = (v1 * cc.y - w1 * ss.y) * qscale;
                    float p0 = (w0 * cc.x + v0 * ss.x) * qscale;
                    float p1 = (w1 * cc.y + v1 * ss.y) * qscale;
                    int col = n0 + warp_n * 64 + d;
                    *(uint32_t*)(Ch + (size_t)row * D_ + col)      = pack2h(q0, q1);
                    *(uint32_t*)(Ch + (size_t)row * D_ + col + 32) = pack2h(p0, p1);
                }
            }
        }
    } else {   // MODE 2
#pragma unroll
        for (int mt = 0; mt < 2; mt++) {
#pragma unroll
            for (int ri = 0; ri < 2; ri++) {
                int row = m0 + warp_m * 32 + mt * 16 + g + ri * 8;
#pragma unroll
                for (int nt = 0; nt < 8; nt++) {
                    int col = n0 + warp_n * 64 + nt * 8 + t2 * 2;
                    *(uint32_t*)(Ch + (size_t)row * D_ + col) =
                        pack2h(acc[mt][nt][ri * 2], acc[mt][nt][ri * 2 + 1]);
                }
            }
        }
    }
}

// log2(e) folded into q so flash softmax can use raw ex2
#define QSCALE_LOG2E (0.125f * 1.44269504088896f)

__global__ void __launch_bounds__(256, 2)
gemm_qkv_mma(const float* __restrict__ cosp, const float* __restrict__ sinp)
{
    const int z = blockIdx.z;
    if (z == 0)
        gemm_core<3>(g_xh, g_wh, nullptr, g_qh, cosp, sinp, QSCALE_LOG2E);
    else if (z == 1)
        gemm_core<3>(g_xh, g_wh + DD_, nullptr, g_kh, cosp, sinp, 1.0f);
    else
        gemm_core<2>(g_xh, g_wh + 2 * (size_t)DD_, nullptr, g_vh,
                     nullptr, nullptr, 1.0f);
}

__global__ void __launch_bounds__(256, 2)
gemm_out_mma(float* __restrict__ out)
{
    gemm_core<0>(g_aoh, g_wh + 3 * (size_t)DD_, out, nullptr,
                 nullptr, nullptr, 1.0f);
}

// ---------------------------------------------------------------------------
// Flash attention on mma.sync, single fp16 pass everywhere.
// Softmax in base-2 (log2e folded into q). CTA: 8 warps, Br=128, Bc=64.
// __launch_bounds__(256,2): 2 CTAs/SM.
// ---------------------------------------------------------------------------
#define FS    72                        // smem row stride in halfwords (144 B)
#define QH_E  0
#define KV_E  (128 * FS)                // 9216
#define ARR_E (64 * FS)                 // 4608
#define STG_E (2 * ARR_E)               // 9216 (kh, vh)
#define FA_BYTES ((KV_E + 2 * STG_E) * 2)   // 55296

__global__ void __launch_bounds__(256, 2)
flash_mma()
{
    extern __shared__ __align__(128) char fsmc[];
    const uint32_t sb = smem_u32(fsmc);
    const int tid = threadIdx.x, lane = tid & 31, wid = tid >> 5;
    const int qt = gridDim.x - 1 - blockIdx.x;        // heavy tiles first
    const int bh = blockIdx.y;
    const int b = bh >> 4, h = bh & 15;
    const int g = lane >> 2, t2 = lane & 3;
    const size_t qtok = (size_t)b * T_ + (size_t)qt * 128;

    // --- issue Q loads ---
#pragma unroll
    for (int i = 0; i < 4; i++) {
        int v = tid + i * 256;                 // 0..1023
        int row = v >> 3, c = v & 7;
        cp16(sb + (uint32_t)(QH_E + row * FS + c * 8) * 2,
             g_qh + (qtok + row) * D_ + h * 64 + c * 8);
    }

    auto issueKV = [&](int kt, int st) {
        const size_t tok = (size_t)b * T_ + (size_t)kt * 64;
#pragma unroll
        for (int i = 0; i < 4; i++) {
            int v = tid + i * 256;             // 0..1023
            int arr = v >> 9, rem = v & 511;   // 0: kh, 1: vh
            int row = rem >> 3, c = rem & 7;
            cp16(sb + (uint32_t)(KV_E + st * STG_E + arr * ARR_E + row * FS + c * 8) * 2,
                 (arr ? g_vh : g_kh) + (tok + row) * D_ + h * 64 + c * 8);
        }
        CP_COMMIT();
    };

    issueKV(0, 0);
    CP_WAIT(0);
    __syncthreads();

    // --- Q fragments into registers ---
    uint32_t qh[4][4];
    {
        uint32_t base_r = (uint32_t)((wid * 16 + (lane & 15)) * FS + ((lane >> 4) & 1) * 8);
#pragma unroll
        for (int kg = 0; kg < 4; kg++) {
            ldsm4(qh[kg][0], qh[kg][1], qh[kg][2], qh[kg][3],
                  sb + (QH_E + base_r + kg * 16) * 2);
        }
    }

    float o[8][4];
#pragma unroll
    for (int nt = 0; nt < 8; nt++)
#pragma unroll
        for (int j = 0; j < 4; j++) o[nt][j] = 0.f;
    float m0r = -INFINITY, m1r = -INFINITY, l0 = 0.f, l1 = 0.f;

    const int nkt = 2 * qt + 2;
    const int row0 = qt * 128 + wid * 16 + g;

    for (int kt = 0; kt < nkt; kt++) {
        if (kt + 1 < nkt) issueKV(kt + 1, (kt + 1) & 1);

        const uint32_t kb_h = sb + (uint32_t)(KV_E + (kt & 1) * STG_E) * 2;
        const uint32_t vb_h = kb_h + ARR_E * 2;

        // ---- S = Q K^T (single pass) ----
        float s[8][4];
#pragma unroll
        for (int nt = 0; nt < 8; nt++)
#pragma unroll
            for (int j = 0; j < 4; j++) s[nt][j] = 0.f;

#pragma unroll
        for (int kg = 0; kg < 4; kg++) {
            const uint32_t brow = (uint32_t)(((lane & 7) + ((lane >> 4) & 1) * 8) * FS
                                             + kg * 16 + ((lane >> 3) & 1) * 8) * 2;
#pragma unroll
            for (int pt = 0; pt < 4; pt++) {
                uint32_t k0, k1, k2, k3;
                ldsm4(k0, k1, k2, k3, kb_h + brow + (uint32_t)(pt * 16 * FS) * 2);
                mma16816(s[2 * pt],     qh[kg][0], qh[kg][1], qh[kg][2], qh[kg][3], k0, k1);
                mma16816(s[2 * pt + 1], qh[kg][0], qh[kg][1], qh[kg][2], qh[kg][3], k2, k3);
            }
        }

        // ---- causal mask (logits are base-2 scaled) ----
        if (kt * 64 + 63 > qt * 128 + wid * 16) {
#pragma unroll
            for (int nt = 0; nt < 8; nt++) {
#pragma unroll
                for (int j = 0; j < 4; j++) {
                    int col = kt * 64 + nt * 8 + t2 * 2 + (j & 1);
                    int row = row0 + (j >> 1) * 8;
                    if (col > row) s[nt][j] = -1e30f;
                }
            }
        }

        // ---- online softmax (base 2) ----
        float mx0 = -INFINITY, mx1 = -INFINITY;
#pragma unroll
        for (int nt = 0; nt < 8; nt++) {
            mx0 = fmaxf(mx0, fmaxf(s[nt][0], s[nt][1]));
            mx1 = fmaxf(mx1, fmaxf(s[nt][2], s[nt][3]));
        }
        mx0 = fmaxf(mx0, __shfl_xor_sync(0xffffffffu, mx0, 1));
        mx0 = fmaxf(mx0, __shfl_xor_sync(0xffffffffu, mx0, 2));
        mx1 = fmaxf(mx1, __shfl_xor_sync(0xffffffffu, mx1, 1));
        mx1 = fmaxf(mx1, __shfl_xor_sync(0xffffffffu, mx1, 2));

        float mn0 = fmaxf(m0r, mx0), mn1 = fmaxf(m1r, mx1);
        float al0 = ex2f(m0r - mn0), al1 = ex2f(m1r - mn1);
        m0r = mn0; m1r = mn1;

        float su0 = 0.f, su1 = 0.f;
#pragma unroll
        for (int nt = 0; nt < 8; nt++) {
            s[nt][0] = ex2f(s[nt][0] - mn0);
            s[nt][1] = ex2f(s[nt][1] - mn0);
            s[nt][2] = ex2f(s[nt][2] - mn1);
            s[nt][3] = ex2f(s[nt][3] - mn1);
            su0 += s[nt][0] + s[nt][1];
            su1 += s[nt][2] + s[nt][3];
        }
        su0 += __shfl_xor_sync(0xffffffffu, su0, 1);
        su0 += __shfl_xor_sync(0xffffffffu, su0, 2);
        su1 += __shfl_xor_sync(0xffffffffu, su1, 1);
        su1 += __shfl_xor_sync(0xffffffffu, su1, 2);
        l0 = l0 * al0 + su0;
        l1 = l1 * al1 + su1;

#pragma unroll
        for (int nt = 0; nt < 8; nt++) {
            o[nt][0] *= al0; o[nt][1] *= al0;
            o[nt][2] *= al1; o[nt][3] *= al1;
        }

        // ---- O += P V (single pass; P rounded to fp16) ----
#pragma unroll
        for (int kk = 0; kk < 4; kk++) {
            uint32_t pah[4];
            pah[0] = pack2h(s[2 * kk][0],     s[2 * kk][1]);
            pah[1] = pack2h(s[2 * kk][2],     s[2 * kk][3]);
            pah[2] = pack2h(s[2 * kk + 1][0], s[2 * kk + 1][1]);
            pah[3] = pack2h(s[2 * kk + 1][2], s[2 * kk + 1][3]);

            const uint32_t vrow = (uint32_t)((kk * 16 + (lane & 7) + ((lane >> 3) & 1) * 8) * FS
                                             + ((lane >> 4) & 1) * 8) * 2;
#pragma unroll
            for (int dg = 0; dg < 4; dg++) {
                uint32_t v0, v1, v2, v3;
                ldsm4t(v0, v1, v2, v3, vb_h + vrow + (uint32_t)(dg * 16) * 2);
                mma16816(o[2 * dg],     pah[0], pah[1], pah[2], pah[3], v0, v1);
                mma16816(o[2 * dg + 1], pah[0], pah[1], pah[2], pah[3], v2, v3);
            }
        }

        if (kt + 1 < nkt) CP_WAIT(0);
        __syncthreads();
    }

    // ---- epilogue: normalize, store fp16 ----
    const float inv0 = 1.0f / l0, inv1 = 1.0f / l1;
    const size_t tok0 = qtok + (size_t)(wid * 16 + g);
#pragma unroll
    for (int nt = 0; nt < 8; nt++) {
        int col = h * 64 + nt * 8 + t2 * 2;
        *(uint32_t*)(g_aoh + tok0 * D_ + col) =
            pack2h(o[nt][0] * inv0, o[nt][1] * inv0);
        *(uint32_t*)(g_aoh + (tok0 + 8) * D_ + col) =
            pack2h(o[nt][2] * inv1, o[nt][3] * inv1);
    }
}

// ---------------------------------------------------------------------------
// Harness entry
// ---------------------------------------------------------------------------
extern "C" void kernel_launch(void* const* d_in, const int* in_sizes, int n_in,
                              void* d_out, int out_size)
{
    const float* x    = (const float*)d_in[0];
    const float* cosp = (const float*)d_in[1];
    const float* sinp = (const float*)d_in[2];
    const float* wq   = (const float*)d_in[3];
    const float* wk   = (const float*)d_in[4];
    const float* wv   = (const float*)d_in[5];
    const float* wo   = (const float*)d_in[6];
    float* out        = (float*)d_out;

    cudaFuncSetAttribute(gemm_qkv_mma,
                         cudaFuncAttributeMaxDynamicSharedMemorySize, GEMM_SMEM_B);
    cudaFuncSetAttribute(gemm_out_mma,
                         cudaFuncAttributeMaxDynamicSharedMemorySize, GEMM_SMEM_B);
    cudaFuncSetAttribute(flash_mma,
                         cudaFuncAttributeMaxDynamicSharedMemorySize, FA_BYTES);

    // 0) fp32 -> fp16 conversions
    {
        int n2x = (M_TOT * D_) / 2;
        split_x_kernel<<<(n2x + 255) / 256, 256>>>(x);
        dim3 wg(DD_ / 2 / 256, 4);
        split_w4_kernel<<<wg, 256>>>(wq, wk, wv, wo);
    }

    // 1) QKV projections with fused RoPE/scale/convert epilogues
    {
        dim3 grid(D_ / 128, M_TOT / 128, 3);
        gemm_qkv_mma<<<grid, 256, GEMM_SMEM_B>>>(cosp, sinp);
    }

    // 2) Causal flash attention -> g_aoh
    {
        dim3 grid(T_ / 128, B_ * H_);
        flash_mma<<<grid, 256, FA_BYTES>>>();
    }

    // 3) Output projection
    {
        dim3 grid(D_ / 128, M_TOT / 128, 1);
        gemm_out_mma<<<grid, 256, GEMM_SMEM_B>>>(out);
    }
}

// round 16
// speedup vs baseline: 2.8971x; 1.0414x over previous
#include <cuda_runtime.h>
#include <cuda_fp16.h>
#include <math.h>
#include <stdint.h>

// Problem dims (fixed by the reference)
#define B_   4
#define T_   2048
#define D_   1024
#define H_   16
#define HD_  64
#define M_TOT (B_*T_)   // 8192
#define DD_  (D_*D_)

// ---------------------------------------------------------------------------
// Device-global scratch (allocation-free rule). Single fp16 everywhere.
// ---------------------------------------------------------------------------
__device__ __align__(128) __half g_xh [M_TOT * D_];
__device__ __align__(128) __half g_qh [M_TOT * D_];
__device__ __align__(128) __half g_kh [M_TOT * D_];
__device__ __align__(128) __half g_vh [M_TOT * D_];
__device__ __align__(128) __half g_aoh[M_TOT * D_];
__device__ __align__(128) __half g_wh [4 * DD_];   // q,k,v,o

// ---------------------------------------------------------------------------
// PTX helpers (target-independent, sm_80-era)
// ---------------------------------------------------------------------------
__device__ __forceinline__ uint32_t smem_u32(const void* p) {
    uint32_t a;
    asm("{ .reg .u64 t; cvta.to.shared.u64 t, %1; cvt.u32.u64 %0, t; }"
        : "=r"(a) : "l"(p));
    return a;
}

__device__ __forceinline__ void cp16(uint32_t dst, const void* src) {
    asm volatile("cp.async.cg.shared.global [%0], [%1], 16;"
                 :: "r"(dst), "l"(src));
}
#define CP_COMMIT() asm volatile("cp.async.commit_group;" ::: "memory")
#define CP_WAIT(n)  asm volatile("cp.async.wait_group %0;" :: "n"(n) : "memory")

__device__ __forceinline__ void ldsm4(uint32_t& r0, uint32_t& r1,
                                      uint32_t& r2, uint32_t& r3, uint32_t a) {
    asm volatile("ldmatrix.sync.aligned.m8n8.x4.shared.b16 {%0,%1,%2,%3}, [%4];"
                 : "=r"(r0), "=r"(r1), "=r"(r2), "=r"(r3) : "r"(a));
}
__device__ __forceinline__ void ldsm4t(uint32_t& r0, uint32_t& r1,
                                       uint32_t& r2, uint32_t& r3, uint32_t a) {
    asm volatile("ldmatrix.sync.aligned.m8n8.x4.trans.shared.b16 {%0,%1,%2,%3}, [%4];"
                 : "=r"(r0), "=r"(r1), "=r"(r2), "=r"(r3) : "r"(a));
}

__device__ __forceinline__ void mma16816(float* c,
                                         uint32_t a0, uint32_t a1,
                                         uint32_t a2, uint32_t a3,
                                         uint32_t b0, uint32_t b1) {
    asm volatile("mma.sync.aligned.m16n8k16.row.col.f32.f16.f16.f32 "
                 "{%0,%1,%2,%3}, {%4,%5,%6,%7}, {%8,%9}, {%0,%1,%2,%3};"
                 : "+f"(c[0]), "+f"(c[1]), "+f"(c[2]), "+f"(c[3])
                 : "r"(a0), "r"(a1), "r"(a2), "r"(a3), "r"(b0), "r"(b1));
}

__device__ __forceinline__ float ex2f(float x) {
    float y;
    asm("ex2.approx.ftz.f32 %0, %1;" : "=f"(y) : "f"(x));
    return y;
}

// exp2 of two fp32 values via the f16x2 pipe; result IS an fp16x2 P fragment.
// lo half <- lo arg, hi half <- hi arg.
__device__ __forceinline__ uint32_t exp2h2(float hi, float lo) {
    uint32_t h, r;
    asm("cvt.rn.f16x2.f32 %0, %1, %2;" : "=r"(h) : "f"(hi), "f"(lo));
    asm("ex2.approx.f16x2 %0, %1;" : "=r"(r) : "r"(h));
    return r;
}
__device__ __forceinline__ void hadd2acc(uint32_t& a, uint32_t v) {
    asm("add.rn.f16x2 %0, %0, %1;" : "+r"(a) : "r"(v));
}
__device__ __forceinline__ float h2tof(uint32_t h) {
    __half2 v;
    *reinterpret_cast<uint32_t*>(&v) = h;
    return __low2float(v) + __high2float(v);
}

__device__ __forceinline__ uint32_t pack2h(float x, float y) {
    return (uint32_t)__half_as_ushort(__float2half(x)) |
           ((uint32_t)__half_as_ushort(__float2half(y)) << 16);
}

// ---------------------------------------------------------------------------
// Input conversion kernels
// ---------------------------------------------------------------------------
__global__ void __launch_bounds__(256)
split_x_kernel(const float* __restrict__ src)
{
    int i = blockIdx.x * 256 + threadIdx.x;
    if (i >= M_TOT * D_ / 2) return;
    float2 a = ((const float2*)src)[i];
    ((uint32_t*)g_xh)[i] = pack2h(a.x, a.y);
}

__global__ void __launch_bounds__(256)
split_w4_kernel(const float* __restrict__ wq, const float* __restrict__ wk,
                const float* __restrict__ wv, const float* __restrict__ wo)
{
    int i = blockIdx.x * 256 + threadIdx.x;           // < DD_/2 exactly
    const float* srcs[4] = { wq, wk, wv, wo };
    float2 a = ((const float2*)srcs[blockIdx.y])[i];
    ((uint32_t*)(g_wh + (size_t)blockIdx.y * DD_))[i] = pack2h(a.x, a.y);
}

// ---------------------------------------------------------------------------
// fp16 single-pass GEMM: C[M,N] = A[M,K] * W[N,K]^T
// CTA tile 128x128, BK=32, 8 warps (4m x 2n), 2-stage cp.async pipeline.
// MODE 0: fp32 out. 2: fp16 out. 3: RoPE+scale fp16 out.
// ---------------------------------------------------------------------------
#define ROWB 40                         // smem row stride in halfwords (80 B)
#define S_AH 0
#define S_BH (128 * ROWB)               // 5120 h
#define STAGE_E (256 * ROWB)            // 10240 h
#define STAGE_B (STAGE_E * 2)           // 20480 B
#define GEMM_SMEM_B (2 * STAGE_B)       // 40960 B

template <int MODE>
__device__ void gemm_core(const __half* __restrict__ Ah,
                          const __half* __restrict__ Bh,
                          float* __restrict__ Cf,
                          __half* __restrict__ Ch,
                          const float* __restrict__ cosp,
                          const float* __restrict__ sinp,
                          float qscale)
{
    extern __shared__ __align__(128) char smem[];
    const uint32_t sb = smem_u32(smem);
    const int tid  = threadIdx.x;
    const int lane = tid & 31;
    const int wid  = tid >> 5;
    const int warp_m = wid & 3;         // 32 rows
    const int warp_n = wid >> 2;        // 64 cols
    const int m0 = blockIdx.y * 128;
    const int n0 = blockIdx.x * 128;

    const int a_row = lane & 15;
    const int a_col = (lane >> 4) << 3;
    const int b_row = (lane & 7) + ((lane >> 4) << 3);
    const int b_col = ((lane >> 3) & 1) << 3;

    float acc[2][8][4];
#pragma unroll
    for (int mt = 0; mt < 2; mt++)
#pragma unroll
        for (int nt = 0; nt < 8; nt++)
#pragma unroll
            for (int r = 0; r < 4; r++) acc[mt][nt][r] = 0.f;

    auto issue = [&](int st, int k0) {
        const uint32_t dstb = sb + st * STAGE_B;
#pragma unroll
        for (int i = 0; i < 4; i++) {
            int v = (tid + (i & 1) * 256);              // 0..511
            int r = v >> 2, c = v & 3;
            if (i < 2)
                cp16(dstb + (uint32_t)(S_AH + r * ROWB + c * 8) * 2,
                     Ah + (size_t)(m0 + r) * D_ + k0 + c * 8);
            else
                cp16(dstb + (uint32_t)(S_BH + r * ROWB + c * 8) * 2,
                     Bh + (size_t)(n0 + r) * D_ + k0 + c * 8);
        }
        CP_COMMIT();
    };

    const int NIT = D_ / 32;                // 32
    issue(0, 0);
    for (int ic = 0; ic < NIT; ic++) {
        if (ic + 1 < NIT) {
            issue((ic + 1) & 1, (ic + 1) * 32);
            CP_WAIT(1);
        } else {
            CP_WAIT(0);
        }
        __syncthreads();

        const uint32_t sa = sb + (ic & 1) * STAGE_B;
#pragma unroll
        for (int ks = 0; ks < 2; ks++) {
            uint32_t ah[2][4];
#pragma unroll
            for (int mt = 0; mt < 2; mt++) {
                uint32_t ra = sa + (uint32_t)((warp_m * 32 + mt * 16 + a_row) * ROWB
                                              + ks * 16 + a_col) * 2;
                ldsm4(ah[mt][0], ah[mt][1], ah[mt][2], ah[mt][3], ra + S_AH * 2);
            }
#pragma unroll
            for (int pt = 0; pt < 4; pt++) {
                uint32_t b0, b1, b2, b3;
                uint32_t rb = sa + (uint32_t)(S_BH + (warp_n * 64 + pt * 16 + b_row) * ROWB
                                              + ks * 16 + b_col) * 2;
                ldsm4(b0, b1, b2, b3, rb);
#pragma unroll
                for (int mt = 0; mt < 2; mt++) {
                    mma16816(acc[mt][2 * pt],     ah[mt][0], ah[mt][1], ah[mt][2], ah[mt][3], b0, b1);
                    mma16816(acc[mt][2 * pt + 1], ah[mt][0], ah[mt][1], ah[mt][2], ah[mt][3], b2, b3);
                }
            }
        }
        __syncthreads();
    }

    const int g = lane >> 2, t2 = lane & 3;
    if (MODE == 0) {
#pragma unroll
        for (int mt = 0; mt < 2; mt++) {
            int r0 = m0 + warp_m * 32 + mt * 16 + g;
#pragma unroll
            for (int nt = 0; nt < 8; nt++) {
                int col = n0 + warp_n * 64 + nt * 8 + t2 * 2;
                *(float2*)(Cf + (size_t)r0 * D_ + col) =
                    make_float2(acc[mt][nt][0], acc[mt][nt][1]);
                *(float2*)(Cf + (size_t)(r0 + 8) * D_ + col) =
                    make_float2(acc[mt][nt][2], acc[mt][nt][3]);
            }
        }
    } else if (MODE == 3) {
        // RoPE: head-local pairs (d, d+32) live in nt and nt+4 (warp_n*64 = head half)
#pragma unroll
        for (int mt = 0; mt < 2; mt++) {
#pragma unroll
            for (int ri = 0; ri < 2; ri++) {
                int row = m0 + warp_m * 32 + mt * 16 + g + ri * 8;
                int t = row & (T_ - 1);
#pragma unroll
                for (int nt = 0; nt < 4; nt++) {
                    int d = nt * 8 + t2 * 2;                  // < 32
                    float2 cc = *(const float2*)(cosp + t * HD_ + d);
                    float2 ss = *(const float2*)(sinp + t * HD_ + d);
                    float v0 = acc[mt][nt][ri * 2],     v1 = acc[mt][nt][ri * 2 + 1];
                    float w0 = acc[mt][nt + 4][ri * 2], w1 = acc[mt][nt + 4][ri * 2 + 1];
                    float q0 = (v0 * cc.x - w0 * ss.x) * qscale;
                    float q1 = (v1 * cc.y - w1 * ss.y) * qscale;
                    float p0 = (w0 * cc.x + v0 * ss.x) * qscale;
                    float p1 = (w1 * cc.y + v1 * ss.y) * qscale;
                    int col = n0 + warp_n * 64 + d;
                    *(uint32_t*)(Ch + (size_t)row * D_ + col)      = pack2h(q0, q1);
                    *(uint32_t*)(Ch + (size_t)row * D_ + col + 32) = pack2h(p0, p1);
                }
            }
        }
    } else {   // MODE 2
#pragma unroll
        for (int mt = 0; mt < 2; mt++) {
#pragma unroll
            for (int ri = 0; ri < 2; ri++) {
                int row = m0 + warp_m * 32 + mt * 16 + g + ri * 8;
#pragma unroll
                for (int nt = 0; nt < 8; nt++) {
                    int col = n0 + warp_n * 64 + nt * 8 + t2 * 2;
                    *(uint32_t*)(Ch + (size_t)row * D_ + col) =
                        pack2h(acc[mt][nt][ri * 2], acc[mt][nt][ri * 2 + 1]);
                }
            }
        }
    }
}

// log2(e) folded into q so flash softmax can use raw ex2
#define QSCALE_LOG2E (0.125f * 1.44269504088896f)

__global__ void __launch_bounds__(256, 2)
gemm_qkv_mma(const float* __restrict__ cosp, const float* __restrict__ sinp)
{
    const int z = blockIdx.z;
    if (z == 0)
        gemm_core<3>(g_xh, g_wh, nullptr, g_qh, cosp, sinp, QSCALE_LOG2E);
    else if (z == 1)
        gemm_core<3>(g_xh, g_wh + DD_, nullptr, g_kh, cosp, sinp, 1.0f);
    else
        gemm_core<2>(g_xh, g_wh + 2 * (size_t)DD_, nullptr, g_vh,
                     nullptr, nullptr, 1.0f);
}

__global__ void __launch_bounds__(256, 2)
gemm_out_mma(float* __restrict__ out)
{
    gemm_core<0>(g_aoh, g_wh + 3 * (size_t)DD_, out, nullptr,
                 nullptr, nullptr, 1.0f);
}

// ---------------------------------------------------------------------------
// Flash attention on mma.sync, single fp16 pass; softmax exp via f16x2 pipe
// (exp output IS the P fragment). Base-2 logits (log2e folded into q).
// CTA: 8 warps, Br=128, Bc=64, double-buffered K/V. 2 CTAs/SM.
// ---------------------------------------------------------------------------
#define FS    72                        // smem row stride in halfwords (144 B)
#define QH_E  0
#define KV_E  (128 * FS)                // 9216
#define ARR_E (64 * FS)                 // 4608
#define STG_E (2 * ARR_E)               // 9216 (kh, vh)
#define FA_BYTES ((KV_E + 2 * STG_E) * 2)   // 55296

__global__ void __launch_bounds__(256, 2)
flash_mma()
{
    extern __shared__ __align__(128) char fsmc[];
    const uint32_t sb = smem_u32(fsmc);
    const int tid = threadIdx.x, lane = tid & 31, wid = tid >> 5;
    const int qt = gridDim.x - 1 - blockIdx.x;        // heavy tiles first
    const int bh = blockIdx.y;
    const int b = bh >> 4, h = bh & 15;
    const int g = lane >> 2, t2 = lane & 3;
    const size_t qtok = (size_t)b * T_ + (size_t)qt * 128;

    // --- issue Q loads ---
#pragma unroll
    for (int i = 0; i < 4; i++) {
        int v = tid + i * 256;                 // 0..1023
        int row = v >> 3, c = v & 7;
        cp16(sb + (uint32_t)(QH_E + row * FS + c * 8) * 2,
             g_qh + (qtok + row) * D_ + h * 64 + c * 8);
    }

    auto issueKV = [&](int kt, int st) {
        const size_t tok = (size_t)b * T_ + (size_t)kt * 64;
#pragma unroll
        for (int i = 0; i < 4; i++) {
            int v = tid + i * 256;             // 0..1023
            int arr = v >> 9, rem = v & 511;   // 0: kh, 1: vh
            int row = rem >> 3, c = rem & 7;
            cp16(sb + (uint32_t)(KV_E + st * STG_E + arr * ARR_E + row * FS + c * 8) * 2,
                 (arr ? g_vh : g_kh) + (tok + row) * D_ + h * 64 + c * 8);
        }
        CP_COMMIT();
    };

    issueKV(0, 0);
    CP_WAIT(0);
    __syncthreads();

    // --- Q fragments into registers ---
    uint32_t qh[4][4];
    {
        uint32_t base_r = (uint32_t)((wid * 16 + (lane & 15)) * FS + ((lane >> 4) & 1) * 8);
#pragma unroll
        for (int kg = 0; kg < 4; kg++) {
            ldsm4(qh[kg][0], qh[kg][1], qh[kg][2], qh[kg][3],
                  sb + (QH_E + base_r + kg * 16) * 2);
        }
    }

    float o[8][4];
#pragma unroll
    for (int nt = 0; nt < 8; nt++)
#pragma unroll
        for (int j = 0; j < 4; j++) o[nt][j] = 0.f;
    float m0r = -INFINITY, m1r = -INFINITY, l0 = 0.f, l1 = 0.f;

    const int nkt = 2 * qt + 2;
    const int row0 = qt * 128 + wid * 16 + g;

    for (int kt = 0; kt < nkt; kt++) {
        if (kt + 1 < nkt) issueKV(kt + 1, (kt + 1) & 1);

        const uint32_t kb_h = sb + (uint32_t)(KV_E + (kt & 1) * STG_E) * 2;
        const uint32_t vb_h = kb_h + ARR_E * 2;

        // ---- S = Q K^T (single pass) ----
        float s[8][4];
#pragma unroll
        for (int nt = 0; nt < 8; nt++)
#pragma unroll
            for (int j = 0; j < 4; j++) s[nt][j] = 0.f;

#pragma unroll
        for (int kg = 0; kg < 4; kg++) {
            const uint32_t brow = (uint32_t)(((lane & 7) + ((lane >> 4) & 1) * 8) * FS
                                             + kg * 16 + ((lane >> 3) & 1) * 8) * 2;
#pragma unroll
            for (int pt = 0; pt < 4; pt++) {
                uint32_t k0, k1, k2, k3;
                ldsm4(k0, k1, k2, k3, kb_h + brow + (uint32_t)(pt * 16 * FS) * 2);
                mma16816(s[2 * pt],     qh[kg][0], qh[kg][1], qh[kg][2], qh[kg][3], k0, k1);
                mma16816(s[2 * pt + 1], qh[kg][0], qh[kg][1], qh[kg][2], qh[kg][3], k2, k3);
            }
        }

        // ---- causal mask (logits are base-2 scaled) ----
        if (kt * 64 + 63 > qt * 128 + wid * 16) {
#pragma unroll
            for (int nt = 0; nt < 8; nt++) {
#pragma unroll
                for (int j = 0; j < 4; j++) {
                    int col = kt * 64 + nt * 8 + t2 * 2 + (j & 1);
                    int row = row0 + (j >> 1) * 8;
                    if (col > row) s[nt][j] = -1e30f;
                }
            }
        }

        // ---- online softmax (base 2) ----
        float mx0 = -INFINITY, mx1 = -INFINITY;
#pragma unroll
        for (int nt = 0; nt < 8; nt++) {
            mx0 = fmaxf(mx0, fmaxf(s[nt][0], s[nt][1]));
            mx1 = fmaxf(mx1, fmaxf(s[nt][2], s[nt][3]));
        }
        mx0 = fmaxf(mx0, __shfl_xor_sync(0xffffffffu, mx0, 1));
        mx0 = fmaxf(mx0, __shfl_xor_sync(0xffffffffu, mx0, 2));
        mx1 = fmaxf(mx1, __shfl_xor_sync(0xffffffffu, mx1, 1));
        mx1 = fmaxf(mx1, __shfl_xor_sync(0xffffffffu, mx1, 2));

        float mn0 = fmaxf(m0r, mx0), mn1 = fmaxf(m1r, mx1);
        float al0 = ex2f(m0r - mn0), al1 = ex2f(m1r - mn1);
        m0r = mn0; m1r = mn1;

        // exp via f16x2: result registers are the P fragments directly.
        uint32_t ph0[8], ph1[8];
        uint32_t ac0a = 0, ac0b = 0, ac1a = 0, ac1b = 0;
#pragma unroll
        for (int nt = 0; nt < 8; nt++) {
            uint32_t p0 = exp2h2(s[nt][1] - mn0, s[nt][0] - mn0);
            uint32_t p1 = exp2h2(s[nt][3] - mn1, s[nt][2] - mn1);
            ph0[nt] = p0; ph1[nt] = p1;
            if (nt & 1) { hadd2acc(ac0b, p0); hadd2acc(ac1b, p1); }
            else        { hadd2acc(ac0a, p0); hadd2acc(ac1a, p1); }
        }
        float su0 = h2tof(ac0a) + h2tof(ac0b);
        float su1 = h2tof(ac1a) + h2tof(ac1b);
        su0 += __shfl_xor_sync(0xffffffffu, su0, 1);
        su0 += __shfl_xor_sync(0xffffffffu, su0, 2);
        su1 += __shfl_xor_sync(0xffffffffu, su1, 1);
        su1 += __shfl_xor_sync(0xffffffffu, su1, 2);
        l0 = l0 * al0 + su0;
        l1 = l1 * al1 + su1;

#pragma unroll
        for (int nt = 0; nt < 8; nt++) {
            o[nt][0] *= al0; o[nt][1] *= al0;
            o[nt][2] *= al1; o[nt][3] *= al1;
        }

        // ---- O += P V (P fragments already packed) ----
#pragma unroll
        for (int kk = 0; kk < 4; kk++) {
            const uint32_t vrow = (uint32_t)((kk * 16 + (lane & 7) + ((lane >> 3) & 1) * 8) * FS
                                             + ((lane >> 4) & 1) * 8) * 2;
#pragma unroll
            for (int dg = 0; dg < 4; dg++) {
                uint32_t v0, v1, v2, v3;
                ldsm4t(v0, v1, v2, v3, vb_h + vrow + (uint32_t)(dg * 16) * 2);
                mma16816(o[2 * dg],     ph0[2 * kk], ph1[2 * kk],
                         ph0[2 * kk + 1], ph1[2 * kk + 1], v0, v1);
                mma16816(o[2 * dg + 1], ph0[2 * kk], ph1[2 * kk],
                         ph0[2 * kk + 1], ph1[2 * kk + 1], v2, v3);
            }
        }

        if (kt + 1 < nkt) CP_WAIT(0);
        __syncthreads();
    }

    // ---- epilogue: normalize, store fp16 ----
    const float inv0 = 1.0f / l0, inv1 = 1.0f / l1;
    const size_t tok0 = qtok + (size_t)(wid * 16 + g);
#pragma unroll
    for (int nt = 0; nt < 8; nt++) {
        int col = h * 64 + nt * 8 + t2 * 2;
        *(uint32_t*)(g_aoh + tok0 * D_ + col) =
            pack2h(o[nt][0] * inv0, o[nt][1] * inv0);
        *(uint32_t*)(g_aoh + (tok0 + 8) * D_ + col) =
            pack2h(o[nt][2] * inv1, o[nt][3] * inv1);
    }
}

// ---------------------------------------------------------------------------
// Harness entry
// ---------------------------------------------------------------------------
extern "C" void kernel_launch(void* const* d_in, const int* in_sizes, int n_in,
                              void* d_out, int out_size)
{
    const float* x    = (const float*)d_in[0];
    const float* cosp = (const float*)d_in[1];
    const float* sinp = (const float*)d_in[2];
    const float* wq   = (const float*)d_in[3];
    const float* wk   = (const float*)d_in[4];
    const float* wv   = (const float*)d_in[5];
    const float* wo   = (const float*)d_in[6];
    float* out        = (float*)d_out;

    cudaFuncSetAttribute(gemm_qkv_mma,
                         cudaFuncAttributeMaxDynamicSharedMemorySize, GEMM_SMEM_B);
    cudaFuncSetAttribute(gemm_out_mma,
                         cudaFuncAttributeMaxDynamicSharedMemorySize, GEMM_SMEM_B);
    cudaFuncSetAttribute(flash_mma,
                         cudaFuncAttributeMaxDynamicSharedMemorySize, FA_BYTES);

    // 0) fp32 -> fp16 conversions
    {
        int n2x = (M_TOT * D_) / 2;
        split_x_kernel<<<(n2x + 255) / 256, 256>>>(x);
        dim3 wg(DD_ / 2 / 256, 4);
        split_w4_kernel<<<wg, 256>>>(wq, wk, wv, wo);
    }

    // 1) QKV projections with fused RoPE/scale/convert epilogues
    {
        dim3 grid(D_ / 128, M_TOT / 128, 3);
        gemm_qkv_mma<<<grid, 256, GEMM_SMEM_B>>>(cosp, sinp);
    }

    // 2) Causal flash attention -> g_aoh
    {
        dim3 grid(T_ / 128, B_ * H_);
        flash_mma<<<grid, 256, FA_BYTES>>>();
    }

    // 3) Output projection
    {
        dim3 grid(D_ / 128, M_TOT / 128, 1);
        gemm_out_mma<<<grid, 256, GEMM_SMEM_B>>>(out);
    }
}